// round 10
// baseline (speedup 1.0000x reference)
#include <cuda_runtime.h>
#include <math.h>

#define B_    64
#define T_    512
#define E_    512
#define H_    1024
#define G4_   4096   /* 4*H */
#define TCH_  128    /* time chunk (xproj scratch + persistent span) */
#define NBLK_ 128    /* persistent grid: 1024 units / 8 per block */
#define UPB_  8      /* hidden units per block */

// ---- global scratch (alloc-free rule: __device__ globals) ----
__device__ float g_xproj[(size_t)B_ * TCH_ * G4_];   // 128 MB chunk slab
__device__ float g_hbuf[2][B_ * H_];                 // h ping-pong
__device__ float g_cst[B_ * H_];                     // c state
__device__ unsigned g_bar[T_];                       // per-step arrival counters

// ---------------- packed f32x2 helpers (bit-exact 2x fp32 FMA) --------------
__device__ __forceinline__ unsigned long long pk2(float x, float y) {
    unsigned long long r;
    unsigned int a = __float_as_uint(x), b = __float_as_uint(y);
    asm("mov.b64 %0, {%1,%2};" : "=l"(r) : "r"(a), "r"(b));
    return r;
}
__device__ __forceinline__ void upk2(unsigned long long v, float& x, float& y) {
    unsigned int a, b;
    asm("mov.b64 {%0,%1}, %2;" : "=r"(a), "=r"(b) : "l"(v));
    x = __uint_as_float(a); y = __uint_as_float(b);
}
__device__ __forceinline__ unsigned long long ffma2(unsigned long long a,
                                                    unsigned long long b,
                                                    unsigned long long c) {
    unsigned long long d;
    asm("fma.rn.f32x2 %0, %1, %2, %3;" : "=l"(d) : "l"(a), "l"(b), "l"(c));
    return d;
}
__device__ __forceinline__ float tanha(float x) {
    float y;
    asm("tanh.approx.f32 %0, %1;" : "=f"(y) : "f"(x));
    return y;
}
__device__ __forceinline__ float sigm(float x) {
    return __fdividef(1.f, 1.f + __expf(-x));
}

// ---------------------------- init ------------------------------------------
__global__ void init_state() {
    int i = blockIdx.x * blockDim.x + threadIdx.x;
    if (i < B_ * H_) { g_hbuf[0][i] = 0.f; g_cst[i] = 0.f; }
    if (i < T_) g_bar[i] = 0u;
}

// ---------------- Phase 1: Xproj chunk = emb[src] @ W_ih + bias -------------
__global__ __launch_bounds__(256) void xproj_gemm(const int* __restrict__ src,
                                                  const float* __restrict__ emb,
                                                  const float* __restrict__ Wih,
                                                  const float* __restrict__ bias,
                                                  int t0) {
    __shared__ __align__(16) float As[16][132];
    __shared__ __align__(16) float Bs[16][64];
    __shared__ int srow[128];

    const int tid = threadIdx.x;
    const int m0 = blockIdx.y * 128;
    const int n0 = blockIdx.x * 64;

    if (tid < 128) {
        int m = m0 + tid;
        int b = m & 63, t = t0 + (m >> 6);
        srow[tid] = src[b * T_ + t];
    }
    __syncthreads();

    const int ty = tid >> 4;
    const int tx = tid & 15;

    unsigned long long acc[4][4];
    #pragma unroll
    for (int i = 0; i < 4; i++)
        #pragma unroll
        for (int j = 0; j < 4; j++) acc[i][j] = 0ull;

    for (int e0 = 0; e0 < E_; e0 += 16) {
        #pragma unroll
        for (int i = 0; i < 2; i++) {
            int idx = tid + i * 256;
            int row = idx >> 2, c4 = idx & 3;
            float4 v = *reinterpret_cast<const float4*>(
                &emb[(size_t)srow[row] * E_ + e0 + c4 * 4]);
            As[c4 * 4 + 0][row] = v.x; As[c4 * 4 + 1][row] = v.y;
            As[c4 * 4 + 2][row] = v.z; As[c4 * 4 + 3][row] = v.w;
        }
        {
            int row = tid >> 4, c4 = tid & 15;
            *reinterpret_cast<float4*>(&Bs[row][c4 * 4]) =
                *reinterpret_cast<const float4*>(
                    &Wih[(size_t)(e0 + row) * G4_ + n0 + c4 * 4]);
        }
        __syncthreads();

        #pragma unroll
        for (int kk = 0; kk < 16; kk++) {
            ulonglong2 a01 = *reinterpret_cast<ulonglong2*>(&As[kk][ty * 8]);
            ulonglong2 a23 = *reinterpret_cast<ulonglong2*>(&As[kk][ty * 8 + 4]);
            unsigned long long a2[4] = {a01.x, a01.y, a23.x, a23.y};
            float4 bv = *reinterpret_cast<float4*>(&Bs[kk][tx * 4]);
            unsigned long long bb[4] = {pk2(bv.x, bv.x), pk2(bv.y, bv.y),
                                        pk2(bv.z, bv.z), pk2(bv.w, bv.w)};
            #pragma unroll
            for (int i = 0; i < 4; i++)
                #pragma unroll
                for (int j = 0; j < 4; j++)
                    acc[i][j] = ffma2(a2[i], bb[j], acc[i][j]);
        }
        __syncthreads();
    }

    float4 b4 = *reinterpret_cast<const float4*>(&bias[n0 + tx * 4]);
    #pragma unroll
    for (int rp = 0; rp < 4; rp++) {
        float r0[4], r1[4];
        #pragma unroll
        for (int j = 0; j < 4; j++) upk2(acc[rp][j], r0[j], r1[j]);
        int m = m0 + ty * 8 + rp * 2;
        float4 o0 = make_float4(r0[0] + b4.x, r0[1] + b4.y, r0[2] + b4.z, r0[3] + b4.w);
        float4 o1 = make_float4(r1[0] + b4.x, r1[1] + b4.y, r1[2] + b4.z, r1[3] + b4.w);
        *reinterpret_cast<float4*>(&g_xproj[(size_t)m * G4_ + n0 + tx * 4]) = o0;
        *reinterpret_cast<float4*>(&g_xproj[(size_t)(m + 1) * G4_ + n0 + tx * 4]) = o1;
    }
}

// ---------------- Phase 2: persistent LSTM over a 128-step chunk ------------
// grid = 128 blocks x 512 threads (all resident, 1/SM). Block p owns units
// u0 = p*8 (32 W_hh columns, gate-interleaved in SMEM: ws[k][j*4+g]).
// Warp w owns batches w*4..+4; lane owns ONE cell (b, j) and all 4 gates:
// z accumulates over all k in 2 f32x2 regs -> no cross-warp reduction at all.
// h staged [b][k] (no transpose), double-buffered, 1 sync per 64-k chunk.
//
// SMEM map (dynamic):
//   [0,      131072)  ws[1024][32]      weights, c' = j*4 + g
//   [131072, 165888)  hs[2][64][68]     h chunk double buffer, [b][k]
//   [165888, 167936)  cs[512]           c state, index = tid
#define SMEM_BYTES_ 167936

__global__ __launch_bounds__(512, 1) void lstm_chunk(const float* __restrict__ Whh,
                                                     int s0) {
    extern __shared__ __align__(16) char smem[];
    float* ws = (float*)smem;
    float* hs = (float*)(smem + 131072);
    float* cs = (float*)(smem + 165888);

    const int tid  = threadIdx.x;
    const int wid  = tid >> 5;
    const int lane = tid & 31;
    const int u0   = blockIdx.x * UPB_;
    const int myb  = wid * 4 + (lane >> 3);      // this lane's batch
    const int j    = lane & 7;                   // this lane's unit

    // ---- load Whh slice, gate-interleaved: ws[k*32 + j*4 + g] ----
    #pragma unroll
    for (int i = 0; i < 16; i++) {
        int idx = tid + i * 512;                 // 0..8191 float4 loads
        int k = idx >> 3, rem = idx & 7, g = rem >> 1, jq = rem & 1;
        float4 v = *reinterpret_cast<const float4*>(
            &Whh[(size_t)k * G4_ + g * H_ + u0 + jq * 4]);
        float* wd = &ws[k * 32 + jq * 16 + g];
        wd[0] = v.x; wd[4] = v.y; wd[8] = v.z; wd[12] = v.w;
    }
    // ---- c state: cs[tid] is this lane's cell (b = tid>>3, j = tid&7) ----
    cs[tid] = g_cst[(tid >> 3) * H_ + u0 + (tid & 7)];
    __syncthreads();

    const int bs = tid >> 3;                     // staging row
    const int ks = (tid & 7) * 8;                // staging col base

    for (int ls = 0; ls < TCH_; ls++) {
        const int s = s0 + ls;
        const float* __restrict__ h_in  = g_hbuf[s & 1];
        float* __restrict__       h_out = g_hbuf[(s + 1) & 1];
        const float* __restrict__ Xp    = g_xproj + (size_t)ls * (B_ * G4_);

        // prefetch Xproj gate values (consumed after the k loop)
        const float* xb = &Xp[(size_t)myb * G4_ + u0 + j];
        float xg0 = __ldg(xb);
        float xg1 = __ldg(xb + H_);
        float xg2 = __ldg(xb + 2 * H_);
        float xg3 = __ldg(xb + 3 * H_);

        unsigned long long acc01 = 0ull, acc23 = 0ull;   // (z_i,z_f),(z_g,z_o)

        // preload chunk 0 staging registers
        float4 r0 = __ldcg(reinterpret_cast<const float4*>(
            &h_in[bs * H_ + ks]));
        float4 r1 = __ldcg(reinterpret_cast<const float4*>(
            &h_in[bs * H_ + ks + 4]));

        for (int ch = 0; ch < 16; ch++) {
            float* buf = hs + (ch & 1) * 4352;
            // stage chunk ch ([b][k], straight copy)
            *reinterpret_cast<float4*>(&buf[bs * 68 + ks])     = r0;
            *reinterpret_cast<float4*>(&buf[bs * 68 + ks + 4]) = r1;
            // prefetch chunk ch+1
            if (ch < 15) {
                r0 = __ldcg(reinterpret_cast<const float4*>(
                    &h_in[bs * H_ + (ch + 1) * 64 + ks]));
                r1 = __ldcg(reinterpret_cast<const float4*>(
                    &h_in[bs * H_ + (ch + 1) * 64 + ks + 4]));
            }
            __syncthreads();

            const float* hb = buf + myb * 68;
            const float* wk = ws + (ch * 64) * 32 + j * 4;
            #pragma unroll
            for (int kq = 0; kq < 16; kq++) {
                float4 h4 = *reinterpret_cast<const float4*>(&hb[kq * 4]);
                float ha[4] = {h4.x, h4.y, h4.z, h4.w};
                #pragma unroll
                for (int m = 0; m < 4; m++) {
                    ulonglong2 wv = *reinterpret_cast<const ulonglong2*>(
                        &wk[(kq * 4 + m) * 32]);
                    unsigned long long hh = pk2(ha[m], ha[m]);
                    acc01 = ffma2(wv.x, hh, acc01);
                    acc23 = ffma2(wv.y, hh, acc23);
                }
            }
        }

        // ---- gates: entirely in registers, one cell per lane ----
        float z0, z1, z2, z3;
        upk2(acc01, z0, z1);
        upk2(acc23, z2, z3);
        z0 += xg0; z1 += xg1; z2 += xg2; z3 += xg3;
        float ig = sigm(z0);
        float fg = sigm(z1);
        float gg = tanha(z2);
        float og = sigm(z3);
        float cn = fg * cs[tid] + ig * gg;
        cs[tid] = cn;
        h_out[myb * H_ + u0 + j] = og * tanha(cn);

        // ---- grid-wide barrier (release arrival, acquire spin) ----
        __threadfence();
        __syncthreads();
        if (tid == 0) {
            asm volatile("red.release.gpu.global.add.u32 [%0], 1;"
                         :: "l"(&g_bar[s]) : "memory");
            unsigned v;
            do {
                asm volatile("ld.acquire.gpu.global.u32 %0, [%1];"
                             : "=r"(v) : "l"(&g_bar[s]) : "memory");
            } while (v < NBLK_);
        }
        __syncthreads();
    }

    // ---- persist c state ----
    g_cst[(tid >> 3) * H_ + u0 + (tid & 7)] = cs[tid];
}

// ------------------------------- output -------------------------------------
// After t=511, h lives in g_hbuf[(511+1)&1] == g_hbuf[0]. Output = [h_T ; c_T].
__global__ void write_out(float* __restrict__ out) {
    int i = blockIdx.x * blockDim.x + threadIdx.x;
    if (i < B_ * H_) {
        out[i] = g_hbuf[0][i];
        out[B_ * H_ + i] = g_cst[i];
    }
}

extern "C" void kernel_launch(void* const* d_in, const int* in_sizes, int n_in,
                              void* d_out, int out_size) {
    (void)in_sizes; (void)n_in; (void)out_size;
    const int*   src  = (const int*)d_in[0];
    const float* emb  = (const float*)d_in[1];
    const float* Wih  = (const float*)d_in[2];
    const float* Whh  = (const float*)d_in[3];
    const float* bias = (const float*)d_in[4];
    float* out = (float*)d_out;

    cudaFuncSetAttribute(lstm_chunk, cudaFuncAttributeMaxDynamicSharedMemorySize,
                         SMEM_BYTES_);

    init_state<<<(B_ * H_ + 255) / 256, 256>>>();
    for (int t0 = 0; t0 < T_; t0 += TCH_) {
        xproj_gemm<<<dim3(G4_ / 64, (TCH_ * B_) / 128), 256>>>(src, emb, Wih,
                                                               bias, t0);
        lstm_chunk<<<NBLK_, 512, SMEM_BYTES_>>>(Whh, t0);
    }
    write_out<<<(B_ * H_ + 255) / 256, 256>>>(out);
}

// round 11
// speedup vs baseline: 1.6880x; 1.6880x over previous
#include <cuda_runtime.h>
#include <math.h>

#define B_    64
#define T_    512
#define E_    512
#define H_    1024
#define G4_   4096   /* 4*H */
#define TCH_  128    /* time chunk (xproj scratch + persistent span) */
#define NBLK_ 128    /* persistent grid: 1024 units / 8 per block */
#define UPB_  8      /* hidden units per block */

// ---- global scratch (alloc-free rule: __device__ globals) ----
__device__ float g_xproj[(size_t)B_ * TCH_ * G4_];   // 128 MB chunk slab
__device__ float g_hbuf[2][H_ * B_];                 // h ping-pong, [unit][batch]!
__device__ float g_cst[B_ * H_];                     // c state, [batch][unit]
__device__ unsigned g_bar[T_];                       // per-step arrival counters

// ---------------- packed f32x2 helpers (bit-exact 2x fp32) ------------------
__device__ __forceinline__ unsigned long long pk2(float x, float y) {
    unsigned long long r;
    unsigned int a = __float_as_uint(x), b = __float_as_uint(y);
    asm("mov.b64 %0, {%1,%2};" : "=l"(r) : "r"(a), "r"(b));
    return r;
}
__device__ __forceinline__ void upk2(unsigned long long v, float& x, float& y) {
    unsigned int a, b;
    asm("mov.b64 {%0,%1}, %2;" : "=r"(a), "=r"(b) : "l"(v));
    x = __uint_as_float(a); y = __uint_as_float(b);
}
__device__ __forceinline__ unsigned long long ffma2(unsigned long long a,
                                                    unsigned long long b,
                                                    unsigned long long c) {
    unsigned long long d;
    asm("fma.rn.f32x2 %0, %1, %2, %3;" : "=l"(d) : "l"(a), "l"(b), "l"(c));
    return d;
}
__device__ __forceinline__ unsigned long long addf2(unsigned long long a,
                                                    unsigned long long b) {
    unsigned long long d;
    asm("add.rn.f32x2 %0, %1, %2;" : "=l"(d) : "l"(a), "l"(b));
    return d;
}
__device__ __forceinline__ float tanha(float x) {
    float y;
    asm("tanh.approx.f32 %0, %1;" : "=f"(y) : "f"(x));
    return y;
}
__device__ __forceinline__ float sigm(float x) {
    return __fdividef(1.f, 1.f + __expf(-x));
}

// ---------------------------- init ------------------------------------------
__global__ void init_state() {
    int i = blockIdx.x * blockDim.x + threadIdx.x;
    if (i < B_ * H_) { g_hbuf[0][i] = 0.f; g_cst[i] = 0.f; }
    if (i < T_) g_bar[i] = 0u;
}

// ---------------- Phase 1: Xproj chunk = emb[src] @ W_ih + bias -------------
__global__ __launch_bounds__(256) void xproj_gemm(const int* __restrict__ src,
                                                  const float* __restrict__ emb,
                                                  const float* __restrict__ Wih,
                                                  const float* __restrict__ bias,
                                                  int t0) {
    __shared__ __align__(16) float As[16][132];
    __shared__ __align__(16) float Bs[16][64];
    __shared__ int srow[128];

    const int tid = threadIdx.x;
    const int m0 = blockIdx.y * 128;
    const int n0 = blockIdx.x * 64;

    if (tid < 128) {
        int m = m0 + tid;
        int b = m & 63, t = t0 + (m >> 6);
        srow[tid] = src[b * T_ + t];
    }
    __syncthreads();

    const int ty = tid >> 4;
    const int tx = tid & 15;

    unsigned long long acc[4][4];
    #pragma unroll
    for (int i = 0; i < 4; i++)
        #pragma unroll
        for (int j = 0; j < 4; j++) acc[i][j] = 0ull;

    for (int e0 = 0; e0 < E_; e0 += 16) {
        #pragma unroll
        for (int i = 0; i < 2; i++) {
            int idx = tid + i * 256;
            int row = idx >> 2, c4 = idx & 3;
            float4 v = *reinterpret_cast<const float4*>(
                &emb[(size_t)srow[row] * E_ + e0 + c4 * 4]);
            As[c4 * 4 + 0][row] = v.x; As[c4 * 4 + 1][row] = v.y;
            As[c4 * 4 + 2][row] = v.z; As[c4 * 4 + 3][row] = v.w;
        }
        {
            int row = tid >> 4, c4 = tid & 15;
            *reinterpret_cast<float4*>(&Bs[row][c4 * 4]) =
                *reinterpret_cast<const float4*>(
                    &Wih[(size_t)(e0 + row) * G4_ + n0 + c4 * 4]);
        }
        __syncthreads();

        #pragma unroll
        for (int kk = 0; kk < 16; kk++) {
            ulonglong2 a01 = *reinterpret_cast<ulonglong2*>(&As[kk][ty * 8]);
            ulonglong2 a23 = *reinterpret_cast<ulonglong2*>(&As[kk][ty * 8 + 4]);
            unsigned long long a2[4] = {a01.x, a01.y, a23.x, a23.y};
            float4 bv = *reinterpret_cast<float4*>(&Bs[kk][tx * 4]);
            unsigned long long bb[4] = {pk2(bv.x, bv.x), pk2(bv.y, bv.y),
                                        pk2(bv.z, bv.z), pk2(bv.w, bv.w)};
            #pragma unroll
            for (int i = 0; i < 4; i++)
                #pragma unroll
                for (int j = 0; j < 4; j++)
                    acc[i][j] = ffma2(a2[i], bb[j], acc[i][j]);
        }
        __syncthreads();
    }

    float4 b4 = *reinterpret_cast<const float4*>(&bias[n0 + tx * 4]);
    #pragma unroll
    for (int rp = 0; rp < 4; rp++) {
        float r0[4], r1[4];
        #pragma unroll
        for (int j = 0; j < 4; j++) upk2(acc[rp][j], r0[j], r1[j]);
        int m = m0 + ty * 8 + rp * 2;
        float4 o0 = make_float4(r0[0] + b4.x, r0[1] + b4.y, r0[2] + b4.z, r0[3] + b4.w);
        float4 o1 = make_float4(r1[0] + b4.x, r1[1] + b4.y, r1[2] + b4.z, r1[3] + b4.w);
        *reinterpret_cast<float4*>(&g_xproj[(size_t)m * G4_ + n0 + tx * 4]) = o0;
        *reinterpret_cast<float4*>(&g_xproj[(size_t)(m + 1) * G4_ + n0 + tx * 4]) = o1;
    }
}

// ---------------- Phase 2: persistent LSTM over a 128-step chunk ------------
// grid = 128 blocks x 256 threads. Block owns units u0..+8 (32 cols, c=g*8+j),
// weights in SMEM read ONCE per step (k-split). Warp w: kq = w&3 (k-quarter),
// chf = w>>2 (col-half). Lane: bpos = lane>>2 (8 batches, f32x2-paired from
// [k][b] smem), cpos = lane&3 (4 cols). acc[4 bpair][4 col] f32x2.
// h gmem layout is [H][B] so staging is a straight conflict-free copy,
// double-buffered, 1 sync/chunk. Partials stay f32x2-packed through the
// k-quarter reduction (add.rn.f32x2).
//
// SMEM (dynamic, 208896 B):
//   [0,      131072)  ws[1024][32]        weights, c = g*8 + j
//   [131072, 165888)  hs[2][64][68]       h chunk double buffer, [k][b]
//   [165888, 198656)  zs2[4][32][32] ull  packed partials [kq][bpair][c]
//   [198656, 206848)  zf[64][32]          reduced z
//   [206848, 208896)  cs[512]             c state
#define SMEM_BYTES_ 208896

__global__ __launch_bounds__(256, 1) void lstm_chunk(const float* __restrict__ Whh,
                                                     int s0) {
    extern __shared__ __align__(16) char smem[];
    float* ws = (float*)smem;
    float* hs = (float*)(smem + 131072);
    unsigned long long* zs2 = (unsigned long long*)(smem + 165888);
    float* zf = (float*)(smem + 198656);
    float* cs = (float*)(smem + 206848);

    const int tid  = threadIdx.x;
    const int w    = tid >> 5;
    const int lane = tid & 31;
    const int u0   = blockIdx.x * UPB_;
    const int kq   = w & 3;                      // k-quarter (256 k)
    const int chf  = w >> 2;                     // col-half (16 cols)
    const int bpos = lane >> 2;                  // 8 batches bpos*8..+8
    const int cpos = lane & 3;                   // 4 cols
    const int cbase = chf * 16 + cpos * 4;       // lane's first col

    // staging map: row skk (0..63), batch group sc (0..3)
    const int skk = (tid & 7) | ((tid >> 5) << 3);
    const int sc  = (tid >> 3) & 3;

    // ---- load Whh slice into smem: ws[k*32 + g*8 + j] ----
    #pragma unroll
    for (int i = 0; i < 32; i++) {
        int idx = tid + i * 256;                 // 0..8191 float4 loads
        int k = idx >> 3, rem = idx & 7, g = rem >> 1, jq = rem & 1;
        float4 v = *reinterpret_cast<const float4*>(
            &Whh[(size_t)k * G4_ + g * H_ + u0 + jq * 4]);
        *reinterpret_cast<float4*>(&ws[k * 32 + g * 8 + jq * 4]) = v;
    }
    // ---- block-private c state: cs[idx], cell (b=idx>>3, j=idx&7) ----
    #pragma unroll
    for (int i = 0; i < 2; i++) {
        int idx = tid + i * 256;
        cs[idx] = g_cst[(idx >> 3) * H_ + u0 + (idx & 7)];
    }
    __syncthreads();

    for (int ls = 0; ls < TCH_; ls++) {
        const int s = s0 + ls;
        const float* __restrict__ h_in  = g_hbuf[s & 1];        // [H][B]
        float* __restrict__       h_out = g_hbuf[(s + 1) & 1];
        const float* __restrict__ Xp    = g_xproj + (size_t)ls * (B_ * G4_);

        unsigned long long acc[4][4];
        #pragma unroll
        for (int a = 0; a < 4; a++)
            #pragma unroll
            for (int c = 0; c < 4; c++) acc[a][c] = 0ull;

        // preload + stage chunk 0
        float4 rn[4];
        #pragma unroll
        for (int q = 0; q < 4; q++)
            rn[q] = __ldcg(reinterpret_cast<const float4*>(
                &h_in[skk * B_ + sc * 16 + q * 4]));
        #pragma unroll
        for (int q = 0; q < 4; q++)
            *reinterpret_cast<float4*>(&hs[skk * 68 + sc * 16 + q * 4]) = rn[q];
        __syncthreads();

        for (int ch = 0; ch < 16; ch++) {
            if (ch < 15) {
                #pragma unroll
                for (int q = 0; q < 4; q++)
                    rn[q] = __ldcg(reinterpret_cast<const float4*>(
                        &h_in[((ch + 1) * 64 + skk) * B_ + sc * 16 + q * 4]));
            }
            const float* buf = hs + (ch & 1) * 4352;
            const float* hch = buf + (kq * 16) * 68 + bpos * 8;
            const float* wch = ws + (ch * 64 + kq * 16) * 32 + cbase;
            #pragma unroll
            for (int kk = 0; kk < 16; kk++) {
                ulonglong2 hA = *reinterpret_cast<const ulonglong2*>(hch + kk * 68);
                ulonglong2 hB = *reinterpret_cast<const ulonglong2*>(hch + kk * 68 + 4);
                float4 wv = *reinterpret_cast<const float4*>(wch + kk * 32);
                unsigned long long w0 = pk2(wv.x, wv.x);
                unsigned long long w1 = pk2(wv.y, wv.y);
                unsigned long long w2 = pk2(wv.z, wv.z);
                unsigned long long w3 = pk2(wv.w, wv.w);
                acc[0][0] = ffma2(hA.x, w0, acc[0][0]);
                acc[1][0] = ffma2(hA.y, w0, acc[1][0]);
                acc[2][0] = ffma2(hB.x, w0, acc[2][0]);
                acc[3][0] = ffma2(hB.y, w0, acc[3][0]);
                acc[0][1] = ffma2(hA.x, w1, acc[0][1]);
                acc[1][1] = ffma2(hA.y, w1, acc[1][1]);
                acc[2][1] = ffma2(hB.x, w1, acc[2][1]);
                acc[3][1] = ffma2(hB.y, w1, acc[3][1]);
                acc[0][2] = ffma2(hA.x, w2, acc[0][2]);
                acc[1][2] = ffma2(hA.y, w2, acc[1][2]);
                acc[2][2] = ffma2(hB.x, w2, acc[2][2]);
                acc[3][2] = ffma2(hB.y, w2, acc[3][2]);
                acc[0][3] = ffma2(hA.x, w3, acc[0][3]);
                acc[1][3] = ffma2(hA.y, w3, acc[1][3]);
                acc[2][3] = ffma2(hB.x, w3, acc[2][3]);
                acc[3][3] = ffma2(hB.y, w3, acc[3][3]);
            }
            if (ch < 15) {
                float* nbuf = hs + ((ch + 1) & 1) * 4352;
                #pragma unroll
                for (int q = 0; q < 4; q++)
                    *reinterpret_cast<float4*>(
                        &nbuf[skk * 68 + sc * 16 + q * 4]) = rn[q];
            }
            __syncthreads();
        }

        // ---- packed k-quarter partials: zs2[kq][bpair][c] ----
        #pragma unroll
        for (int bp = 0; bp < 4; bp++) {
            unsigned long long* zp =
                zs2 + kq * 1024 + (bpos * 4 + bp) * 32 + cbase;
            *reinterpret_cast<ulonglong2*>(zp) =
                make_ulonglong2(acc[bp][0], acc[bp][1]);
            *reinterpret_cast<ulonglong2*>(zp + 2) =
                make_ulonglong2(acc[bp][2], acc[bp][3]);
        }
        __syncthreads();

        // ---- packed reduction over 4 kq + Xproj; thread: bpair, 4 cols ----
        {
            int bpair = tid >> 3;
            int c0 = (tid & 7) * 4;
            unsigned long long s0a = 0ull, s1a = 0ull, s2a = 0ull, s3a = 0ull;
            #pragma unroll
            for (int q = 0; q < 4; q++) {
                const unsigned long long* zp = zs2 + q * 1024 + bpair * 32 + c0;
                ulonglong2 z01 = *reinterpret_cast<const ulonglong2*>(zp);
                ulonglong2 z23 = *reinterpret_cast<const ulonglong2*>(zp + 2);
                s0a = addf2(s0a, z01.x); s1a = addf2(s1a, z01.y);
                s2a = addf2(s2a, z23.x); s3a = addf2(s3a, z23.y);
            }
            int b = bpair * 2, g = c0 >> 3, j0 = c0 & 7;
            const float* xa = &Xp[(size_t)b * G4_ + g * H_ + u0 + j0];
            float4 x0 = __ldg(reinterpret_cast<const float4*>(xa));
            float4 x1 = __ldg(reinterpret_cast<const float4*>(xa + G4_));
            s0a = addf2(s0a, pk2(x0.x, x1.x));
            s1a = addf2(s1a, pk2(x0.y, x1.y));
            s2a = addf2(s2a, pk2(x0.z, x1.z));
            s3a = addf2(s3a, pk2(x0.w, x1.w));
            float l0, h0, l1, h1, l2, h2, l3, h3;
            upk2(s0a, l0, h0); upk2(s1a, l1, h1);
            upk2(s2a, l2, h2); upk2(s3a, l3, h3);
            *reinterpret_cast<float4*>(&zf[b * 32 + c0]) =
                make_float4(l0, l1, l2, l3);
            *reinterpret_cast<float4*>(&zf[(b + 1) * 32 + c0]) =
                make_float4(h0, h1, h2, h3);
        }
        __syncthreads();

        // ---- gate update: 2 cells per thread ----
        #pragma unroll
        for (int s2i = 0; s2i < 2; s2i++) {
            int idx = tid + s2i * 256;
            int b = idx >> 3, j = idx & 7;
            float zi  = zf[b * 32 + j];
            float zff = zf[b * 32 + 8 + j];
            float zg  = zf[b * 32 + 16 + j];
            float zo  = zf[b * 32 + 24 + j];
            float ig = sigm(zi);
            float fg = sigm(zff);
            float gg = tanha(zg);
            float og = sigm(zo);
            float cn = fg * cs[idx] + ig * gg;
            cs[idx] = cn;
            h_out[(u0 + j) * B_ + b] = og * tanha(cn);   // [H][B] layout
        }

        // ---- grid-wide barrier (release arrival, acquire spin) ----
        __threadfence();
        __syncthreads();
        if (tid == 0) {
            asm volatile("red.release.gpu.global.add.u32 [%0], 1;"
                         :: "l"(&g_bar[s]) : "memory");
            unsigned v;
            do {
                asm volatile("ld.acquire.gpu.global.u32 %0, [%1];"
                             : "=r"(v) : "l"(&g_bar[s]) : "memory");
            } while (v < NBLK_);
        }
        __syncthreads();
    }

    // ---- persist c state ----
    #pragma unroll
    for (int i = 0; i < 2; i++) {
        int idx = tid + i * 256;
        g_cst[(idx >> 3) * H_ + u0 + (idx & 7)] = cs[idx];
    }
}

// ------------------------------- output -------------------------------------
// After t=511, h lives in g_hbuf[0] with [H][B] layout. Output = [h_T ; c_T],
// both [B][H].
__global__ void write_out(float* __restrict__ out) {
    int i = blockIdx.x * blockDim.x + threadIdx.x;
    if (i < B_ * H_) {
        int b = i >> 10, u = i & 1023;           // H_ = 1024
        out[i] = g_hbuf[0][u * B_ + b];
        out[B_ * H_ + i] = g_cst[i];
    }
}

extern "C" void kernel_launch(void* const* d_in, const int* in_sizes, int n_in,
                              void* d_out, int out_size) {
    (void)in_sizes; (void)n_in; (void)out_size;
    const int*   src  = (const int*)d_in[0];
    const float* emb  = (const float*)d_in[1];
    const float* Wih  = (const float*)d_in[2];
    const float* Whh  = (const float*)d_in[3];
    const float* bias = (const float*)d_in[4];
    float* out = (float*)d_out;

    cudaFuncSetAttribute(lstm_chunk, cudaFuncAttributeMaxDynamicSharedMemorySize,
                         SMEM_BYTES_);

    init_state<<<(B_ * H_ + 255) / 256, 256>>>();
    for (int t0 = 0; t0 < T_; t0 += TCH_) {
        xproj_gemm<<<dim3(G4_ / 64, (TCH_ * B_) / 128), 256>>>(src, emb, Wih,
                                                               bias, t0);
        lstm_chunk<<<NBLK_, 256, SMEM_BYTES_>>>(Whh, t0);
    }
    write_out<<<(B_ * H_ + 255) / 256, 256>>>(out);
}

// round 12
// speedup vs baseline: 1.9467x; 1.1533x over previous
#include <cuda_runtime.h>
#include <math.h>

#define B_    64
#define T_    512
#define E_    512
#define H_    1024
#define G4_   4096   /* 4*H */
#define TCH_  128    /* time chunk (xproj scratch + persistent span) */
#define NBLK_ 128    /* persistent grid: 1024 units / 8 per block */
#define UPB_  8      /* hidden units per block */

// ---- global scratch (alloc-free rule: __device__ globals) ----
__device__ float g_xproj[(size_t)B_ * TCH_ * G4_];   // 128 MB chunk slab
__device__ float g_hbuf[2][H_ * B_];                 // h ping-pong, [unit][batch]
__device__ float g_cst[B_ * H_];                     // c state, [batch][unit]
__device__ unsigned g_bar[T_];                       // per-step arrival counters

// ---------------- packed f32x2 helpers (bit-exact 2x fp32) ------------------
__device__ __forceinline__ unsigned long long pk2(float x, float y) {
    unsigned long long r;
    unsigned int a = __float_as_uint(x), b = __float_as_uint(y);
    asm("mov.b64 %0, {%1,%2};" : "=l"(r) : "r"(a), "r"(b));
    return r;
}
__device__ __forceinline__ void upk2(unsigned long long v, float& x, float& y) {
    unsigned int a, b;
    asm("mov.b64 {%0,%1}, %2;" : "=r"(a), "=r"(b) : "l"(v));
    x = __uint_as_float(a); y = __uint_as_float(b);
}
__device__ __forceinline__ unsigned long long ffma2(unsigned long long a,
                                                    unsigned long long b,
                                                    unsigned long long c) {
    unsigned long long d;
    asm("fma.rn.f32x2 %0, %1, %2, %3;" : "=l"(d) : "l"(a), "l"(b), "l"(c));
    return d;
}
__device__ __forceinline__ unsigned long long addf2(unsigned long long a,
                                                    unsigned long long b) {
    unsigned long long d;
    asm("add.rn.f32x2 %0, %1, %2;" : "=l"(d) : "l"(a), "l"(b));
    return d;
}
__device__ __forceinline__ float tanha(float x) {
    float y;
    asm("tanh.approx.f32 %0, %1;" : "=f"(y) : "f"(x));
    return y;
}
__device__ __forceinline__ float sigm(float x) {
    return __fdividef(1.f, 1.f + __expf(-x));
}

// ---------------------------- init ------------------------------------------
__global__ void init_state() {
    int i = blockIdx.x * blockDim.x + threadIdx.x;
    if (i < B_ * H_) { g_hbuf[0][i] = 0.f; g_cst[i] = 0.f; }
    if (i < T_) g_bar[i] = 0u;
}

// ---------------- Phase 1: Xproj chunk = emb[src] @ W_ih + bias -------------
__global__ __launch_bounds__(256) void xproj_gemm(const int* __restrict__ src,
                                                  const float* __restrict__ emb,
                                                  const float* __restrict__ Wih,
                                                  const float* __restrict__ bias,
                                                  int t0) {
    __shared__ __align__(16) float As[16][132];
    __shared__ __align__(16) float Bs[16][64];
    __shared__ int srow[128];

    const int tid = threadIdx.x;
    const int m0 = blockIdx.y * 128;
    const int n0 = blockIdx.x * 64;

    if (tid < 128) {
        int m = m0 + tid;
        int b = m & 63, t = t0 + (m >> 6);
        srow[tid] = src[b * T_ + t];
    }
    __syncthreads();

    const int ty = tid >> 4;
    const int tx = tid & 15;

    unsigned long long acc[4][4];
    #pragma unroll
    for (int i = 0; i < 4; i++)
        #pragma unroll
        for (int j = 0; j < 4; j++) acc[i][j] = 0ull;

    for (int e0 = 0; e0 < E_; e0 += 16) {
        #pragma unroll
        for (int i = 0; i < 2; i++) {
            int idx = tid + i * 256;
            int row = idx >> 2, c4 = idx & 3;
            float4 v = *reinterpret_cast<const float4*>(
                &emb[(size_t)srow[row] * E_ + e0 + c4 * 4]);
            As[c4 * 4 + 0][row] = v.x; As[c4 * 4 + 1][row] = v.y;
            As[c4 * 4 + 2][row] = v.z; As[c4 * 4 + 3][row] = v.w;
        }
        {
            int row = tid >> 4, c4 = tid & 15;
            *reinterpret_cast<float4*>(&Bs[row][c4 * 4]) =
                *reinterpret_cast<const float4*>(
                    &Wih[(size_t)(e0 + row) * G4_ + n0 + c4 * 4]);
        }
        __syncthreads();

        #pragma unroll
        for (int kk = 0; kk < 16; kk++) {
            ulonglong2 a01 = *reinterpret_cast<ulonglong2*>(&As[kk][ty * 8]);
            ulonglong2 a23 = *reinterpret_cast<ulonglong2*>(&As[kk][ty * 8 + 4]);
            unsigned long long a2[4] = {a01.x, a01.y, a23.x, a23.y};
            float4 bv = *reinterpret_cast<float4*>(&Bs[kk][tx * 4]);
            unsigned long long bb[4] = {pk2(bv.x, bv.x), pk2(bv.y, bv.y),
                                        pk2(bv.z, bv.z), pk2(bv.w, bv.w)};
            #pragma unroll
            for (int i = 0; i < 4; i++)
                #pragma unroll
                for (int j = 0; j < 4; j++)
                    acc[i][j] = ffma2(a2[i], bb[j], acc[i][j]);
        }
        __syncthreads();
    }

    float4 b4 = *reinterpret_cast<const float4*>(&bias[n0 + tx * 4]);
    #pragma unroll
    for (int rp = 0; rp < 4; rp++) {
        float r0[4], r1[4];
        #pragma unroll
        for (int j = 0; j < 4; j++) upk2(acc[rp][j], r0[j], r1[j]);
        int m = m0 + ty * 8 + rp * 2;
        float4 o0 = make_float4(r0[0] + b4.x, r0[1] + b4.y, r0[2] + b4.z, r0[3] + b4.w);
        float4 o1 = make_float4(r1[0] + b4.x, r1[1] + b4.y, r1[2] + b4.z, r1[3] + b4.w);
        *reinterpret_cast<float4*>(&g_xproj[(size_t)m * G4_ + n0 + tx * 4]) = o0;
        *reinterpret_cast<float4*>(&g_xproj[(size_t)(m + 1) * G4_ + n0 + tx * 4]) = o1;
    }
}

// ---------------- Phase 2: persistent LSTM over a 128-step chunk ------------
// grid = 128 blocks x 512 threads (16 warps, 4/SMSP). Block owns units u0..+8
// (32 cols, c = g*8 + j), weights in SMEM read ONCE per step.
// Warp w: kq = w&7 (4-k slice within each staged 32-k chunk), chf = w>>3
// (16-col half). Lane: bpos = lane>>2 (8 batches, f32x2-paired), cpos = lane&3
// (4 cols). acc[4 bpair][4 col] f32x2 accumulates k in {ch*32+kq*4 ..+4} over
// all 32 chunks. 8-way packed partial reduction (add.rn.f32x2) afterwards.
// h gmem layout [H][B] -> staging is a straight conflict-free float4 copy,
// double-buffered, 1 sync/chunk.
//
// SMEM (dynamic, 224256 B):
//   [0,      131072)  ws[1024][32]        weights, c = g*8 + j
//   [131072, 148480)  hs[2][32][68]       h chunk double buffer, [k][b]
//   [148480, 214016)  zs2[8][32][32] ull  packed partials [kq][bpair][c]
//   [214016, 222208)  zf[64][32]          reduced z
//   [222208, 224256)  cs[512]             c state
#define SMEM_BYTES_ 224256

__global__ __launch_bounds__(512, 1) void lstm_chunk(const float* __restrict__ Whh,
                                                     int s0) {
    extern __shared__ __align__(16) char smem[];
    float* ws = (float*)smem;
    float* hs = (float*)(smem + 131072);
    unsigned long long* zs2 = (unsigned long long*)(smem + 148480);
    float* zf = (float*)(smem + 214016);
    float* cs = (float*)(smem + 222208);

    const int tid  = threadIdx.x;
    const int w    = tid >> 5;
    const int lane = tid & 31;
    const int u0   = blockIdx.x * UPB_;
    const int kq   = w & 7;                      // 4-k slice within chunk
    const int chf  = w >> 3;                     // col-half (16 cols)
    const int bpos = lane >> 2;                  // 8 batches bpos*8..+8
    const int cpos = lane & 3;                   // 4 cols
    const int cbase = chf * 16 + cpos * 4;       // lane's first col

    // staging map: one float4 per thread per chunk
    const int srow = tid >> 4;                   // 0..31 (k within chunk)
    const int scol = (tid & 15) * 4;             // batch base

    // ---- load Whh slice into smem: ws[k*32 + g*8 + j] ----
    #pragma unroll
    for (int i = 0; i < 16; i++) {
        int idx = tid + i * 512;                 // 0..8191 float4 loads
        int k = idx >> 3, rem = idx & 7, g = rem >> 1, jq = rem & 1;
        float4 v = *reinterpret_cast<const float4*>(
            &Whh[(size_t)k * G4_ + g * H_ + u0 + jq * 4]);
        *reinterpret_cast<float4*>(&ws[k * 32 + g * 8 + jq * 4]) = v;
    }
    // ---- block-private c state: cs[tid], cell (b = tid>>3, j = tid&7) ----
    cs[tid] = g_cst[(tid >> 3) * H_ + u0 + (tid & 7)];
    __syncthreads();

    for (int ls = 0; ls < TCH_; ls++) {
        const int s = s0 + ls;
        const float* __restrict__ h_in  = g_hbuf[s & 1];        // [H][B]
        float* __restrict__       h_out = g_hbuf[(s + 1) & 1];
        const float* __restrict__ Xp    = g_xproj + (size_t)ls * (B_ * G4_);

        unsigned long long acc[4][4];
        #pragma unroll
        for (int a = 0; a < 4; a++)
            #pragma unroll
            for (int c = 0; c < 4; c++) acc[a][c] = 0ull;

        // preload + stage chunk 0
        float4 rn = __ldcg(reinterpret_cast<const float4*>(
            &h_in[srow * B_ + scol]));
        *reinterpret_cast<float4*>(&hs[srow * 68 + scol]) = rn;
        __syncthreads();

        for (int ch = 0; ch < 32; ch++) {
            if (ch < 31) {
                rn = __ldcg(reinterpret_cast<const float4*>(
                    &h_in[((ch + 1) * 32 + srow) * B_ + scol]));
            }
            const float* buf = hs + (ch & 1) * 2176;
            const float* hch = buf + (kq * 4) * 68 + bpos * 8;
            const float* wch = ws + (ch * 32 + kq * 4) * 32 + cbase;
            #pragma unroll
            for (int kk = 0; kk < 4; kk++) {
                ulonglong2 hA = *reinterpret_cast<const ulonglong2*>(hch + kk * 68);
                ulonglong2 hB = *reinterpret_cast<const ulonglong2*>(hch + kk * 68 + 4);
                float4 wv = *reinterpret_cast<const float4*>(wch + kk * 32);
                unsigned long long w0 = pk2(wv.x, wv.x);
                unsigned long long w1 = pk2(wv.y, wv.y);
                unsigned long long w2 = pk2(wv.z, wv.z);
                unsigned long long w3 = pk2(wv.w, wv.w);
                acc[0][0] = ffma2(hA.x, w0, acc[0][0]);
                acc[1][0] = ffma2(hA.y, w0, acc[1][0]);
                acc[2][0] = ffma2(hB.x, w0, acc[2][0]);
                acc[3][0] = ffma2(hB.y, w0, acc[3][0]);
                acc[0][1] = ffma2(hA.x, w1, acc[0][1]);
                acc[1][1] = ffma2(hA.y, w1, acc[1][1]);
                acc[2][1] = ffma2(hB.x, w1, acc[2][1]);
                acc[3][1] = ffma2(hB.y, w1, acc[3][1]);
                acc[0][2] = ffma2(hA.x, w2, acc[0][2]);
                acc[1][2] = ffma2(hA.y, w2, acc[1][2]);
                acc[2][2] = ffma2(hB.x, w2, acc[2][2]);
                acc[3][2] = ffma2(hB.y, w2, acc[3][2]);
                acc[0][3] = ffma2(hA.x, w3, acc[0][3]);
                acc[1][3] = ffma2(hA.y, w3, acc[1][3]);
                acc[2][3] = ffma2(hB.x, w3, acc[2][3]);
                acc[3][3] = ffma2(hB.y, w3, acc[3][3]);
            }
            if (ch < 31) {
                float* nbuf = hs + ((ch + 1) & 1) * 2176;
                *reinterpret_cast<float4*>(&nbuf[srow * 68 + scol]) = rn;
            }
            __syncthreads();
        }

        // ---- packed k-slice partials: zs2[kq][bpair][c] ----
        #pragma unroll
        for (int bp = 0; bp < 4; bp++) {
            unsigned long long* zp =
                zs2 + kq * 1024 + (bpos * 4 + bp) * 32 + cbase;
            *reinterpret_cast<ulonglong2*>(zp) =
                make_ulonglong2(acc[bp][0], acc[bp][1]);
            *reinterpret_cast<ulonglong2*>(zp + 2) =
                make_ulonglong2(acc[bp][2], acc[bp][3]);
        }
        __syncthreads();

        // ---- packed reduction over 8 kq + Xproj; thread: bpair, 2 cols ----
        {
            int bpair = tid >> 4;                // 0..31
            int c0 = (tid & 15) * 2;             // even col
            unsigned long long s0a = 0ull, s1a = 0ull;
            #pragma unroll
            for (int q = 0; q < 8; q++) {
                ulonglong2 z01 = *reinterpret_cast<const ulonglong2*>(
                    zs2 + q * 1024 + bpair * 32 + c0);
                s0a = addf2(s0a, z01.x);
                s1a = addf2(s1a, z01.y);
            }
            int b = bpair * 2, g = c0 >> 3, j0 = c0 & 7;
            const float* xa = &Xp[(size_t)b * G4_ + g * H_ + u0 + j0];
            float2 x0 = *reinterpret_cast<const float2*>(xa);        // b, cols c0,c0+1
            float2 x1 = *reinterpret_cast<const float2*>(xa + G4_);  // b+1
            s0a = addf2(s0a, pk2(x0.x, x1.x));
            s1a = addf2(s1a, pk2(x0.y, x1.y));
            float l0, h0, l1, h1;
            upk2(s0a, l0, h0);
            upk2(s1a, l1, h1);
            *reinterpret_cast<float2*>(&zf[b * 32 + c0]) = make_float2(l0, l1);
            *reinterpret_cast<float2*>(&zf[(b + 1) * 32 + c0]) = make_float2(h0, h1);
        }
        __syncthreads();

        // ---- gate update: one cell per thread ----
        {
            int b = tid >> 3, j = tid & 7;
            float zi  = zf[b * 32 + j];
            float zff = zf[b * 32 + 8 + j];
            float zg  = zf[b * 32 + 16 + j];
            float zo  = zf[b * 32 + 24 + j];
            float ig = sigm(zi);
            float fg = sigm(zff);
            float gg = tanha(zg);
            float og = sigm(zo);
            float cn = fg * cs[tid] + ig * gg;
            cs[tid] = cn;
            h_out[(u0 + j) * B_ + b] = og * tanha(cn);   // [H][B] layout
        }

        // ---- grid-wide barrier (release arrival, acquire spin) ----
        __threadfence();
        __syncthreads();
        if (tid == 0) {
            asm volatile("red.release.gpu.global.add.u32 [%0], 1;"
                         :: "l"(&g_bar[s]) : "memory");
            unsigned v;
            do {
                asm volatile("ld.acquire.gpu.global.u32 %0, [%1];"
                             : "=r"(v) : "l"(&g_bar[s]) : "memory");
            } while (v < NBLK_);
        }
        __syncthreads();
    }

    // ---- persist c state ----
    g_cst[(tid >> 3) * H_ + u0 + (tid & 7)] = cs[tid];
}

// ------------------------------- output -------------------------------------
// After t=511, h lives in g_hbuf[0] with [H][B] layout. Output = [h_T ; c_T],
// both [B][H].
__global__ void write_out(float* __restrict__ out) {
    int i = blockIdx.x * blockDim.x + threadIdx.x;
    if (i < B_ * H_) {
        int b = i >> 10, u = i & 1023;           // H_ = 1024
        out[i] = g_hbuf[0][u * B_ + b];
        out[B_ * H_ + i] = g_cst[i];
    }
}

extern "C" void kernel_launch(void* const* d_in, const int* in_sizes, int n_in,
                              void* d_out, int out_size) {
    (void)in_sizes; (void)n_in; (void)out_size;
    const int*   src  = (const int*)d_in[0];
    const float* emb  = (const float*)d_in[1];
    const float* Wih  = (const float*)d_in[2];
    const float* Whh  = (const float*)d_in[3];
    const float* bias = (const float*)d_in[4];
    float* out = (float*)d_out;

    cudaFuncSetAttribute(lstm_chunk, cudaFuncAttributeMaxDynamicSharedMemorySize,
                         SMEM_BYTES_);

    // Launched twice on purpose: shifts launch indices so ncu's fixed
    // "-s 5 -c 1" capture window lands on lstm_chunk (launch #6) instead of
    // xproj_gemm. init_state is idempotent.
    init_state<<<(B_ * H_ + 255) / 256, 256>>>();
    init_state<<<(B_ * H_ + 255) / 256, 256>>>();
    for (int t0 = 0; t0 < T_; t0 += TCH_) {
        xproj_gemm<<<dim3(G4_ / 64, (TCH_ * B_) / 128), 256>>>(src, emb, Wih,
                                                               bias, t0);
        lstm_chunk<<<NBLK_, 512, SMEM_BYTES_>>>(Whh, t0);
    }
    write_out<<<(B_ * H_ + 255) / 256, 256>>>(out);
}

// round 14
// speedup vs baseline: 2.5145x; 1.2916x over previous
#include <cuda_runtime.h>
#include <cuda_bf16.h>
#include <math.h>

#define B_    64
#define T_    512
#define E_    512
#define H_    1024
#define G4_   4096   /* 4*H */
#define TCH_  128    /* time chunk (xproj scratch + persistent span) */
#define NBLK_ 128    /* persistent grid */
#define UPB_  8      /* hidden units per block */

// ---- global scratch (alloc-free rule: __device__ globals) ----
__device__ float g_xproj[(size_t)B_ * TCH_ * G4_];     // 128 MB chunk slab
__device__ __nv_bfloat16 g_hbf_hi[2][B_ * H_];         // h bf16 hi, [B][H]
__device__ __nv_bfloat16 g_hbf_lo[2][B_ * H_];         // h bf16 lo
__device__ float g_hfin[B_ * H_];                      // final h fp32 [B][H]
__device__ float g_cst[B_ * H_];                       // c state [B][H]
__device__ unsigned g_bar[T_];                         // per-step arrivals

// ---------------- packed f32x2 helpers (xproj) ------------------------------
__device__ __forceinline__ unsigned long long pk2(float x, float y) {
    unsigned long long r;
    unsigned int a = __float_as_uint(x), b = __float_as_uint(y);
    asm("mov.b64 %0, {%1,%2};" : "=l"(r) : "r"(a), "r"(b));
    return r;
}
__device__ __forceinline__ void upk2(unsigned long long v, float& x, float& y) {
    unsigned int a, b;
    asm("mov.b64 {%0,%1}, %2;" : "=r"(a), "=r"(b) : "l"(v));
    x = __uint_as_float(a); y = __uint_as_float(b);
}
__device__ __forceinline__ unsigned long long ffma2(unsigned long long a,
                                                    unsigned long long b,
                                                    unsigned long long c) {
    unsigned long long d;
    asm("fma.rn.f32x2 %0, %1, %2, %3;" : "=l"(d) : "l"(a), "l"(b), "l"(c));
    return d;
}
__device__ __forceinline__ float tanha(float x) {
    float y;
    asm("tanh.approx.f32 %0, %1;" : "=f"(y) : "f"(x));
    return y;
}
__device__ __forceinline__ float sigm(float x) {
    return __fdividef(1.f, 1.f + __expf(-x));
}
__device__ __forceinline__ unsigned pkbf_hi(float a, float b) {
    unsigned short x = __bfloat16_as_ushort(__float2bfloat16(a));
    unsigned short y = __bfloat16_as_ushort(__float2bfloat16(b));
    return (unsigned)x | ((unsigned)y << 16);
}

// mma.sync m16n8k16 bf16 (base sm_80+ instruction -> OK for plain sm_103)
__device__ __forceinline__ void mma16816(float& c0, float& c1, float& c2, float& c3,
                                         unsigned a0, unsigned a1, unsigned a2,
                                         unsigned a3, unsigned b0, unsigned b1) {
    asm volatile(
        "mma.sync.aligned.m16n8k16.row.col.f32.bf16.bf16.f32 "
        "{%0,%1,%2,%3},{%4,%5,%6,%7},{%8,%9},{%0,%1,%2,%3};"
        : "+f"(c0), "+f"(c1), "+f"(c2), "+f"(c3)
        : "r"(a0), "r"(a1), "r"(a2), "r"(a3), "r"(b0), "r"(b1));
}

// ---------------------------- init ------------------------------------------
__global__ void init_state() {
    int i = blockIdx.x * blockDim.x + threadIdx.x;
    if (i < B_ * H_) {
        g_hbf_hi[0][i] = __ushort_as_bfloat16(0);
        g_hbf_lo[0][i] = __ushort_as_bfloat16(0);
        g_cst[i] = 0.f;
    }
    if (i < T_) g_bar[i] = 0u;
}

// ---------------- Phase 1: Xproj chunk = emb[src] @ W_ih + bias -------------
__global__ __launch_bounds__(256) void xproj_gemm(const int* __restrict__ src,
                                                  const float* __restrict__ emb,
                                                  const float* __restrict__ Wih,
                                                  const float* __restrict__ bias,
                                                  int t0) {
    __shared__ __align__(16) float As[16][132];
    __shared__ __align__(16) float Bs[16][64];
    __shared__ int srow[128];

    const int tid = threadIdx.x;
    const int m0 = blockIdx.y * 128;
    const int n0 = blockIdx.x * 64;

    if (tid < 128) {
        int m = m0 + tid;
        int b = m & 63, t = t0 + (m >> 6);
        srow[tid] = src[b * T_ + t];
    }
    __syncthreads();

    const int ty = tid >> 4;
    const int tx = tid & 15;

    unsigned long long acc[4][4];
    #pragma unroll
    for (int i = 0; i < 4; i++)
        #pragma unroll
        for (int j = 0; j < 4; j++) acc[i][j] = 0ull;

    for (int e0 = 0; e0 < E_; e0 += 16) {
        #pragma unroll
        for (int i = 0; i < 2; i++) {
            int idx = tid + i * 256;
            int row = idx >> 2, c4 = idx & 3;
            float4 v = *reinterpret_cast<const float4*>(
                &emb[(size_t)srow[row] * E_ + e0 + c4 * 4]);
            As[c4 * 4 + 0][row] = v.x; As[c4 * 4 + 1][row] = v.y;
            As[c4 * 4 + 2][row] = v.z; As[c4 * 4 + 3][row] = v.w;
        }
        {
            int row = tid >> 4, c4 = tid & 15;
            *reinterpret_cast<float4*>(&Bs[row][c4 * 4]) =
                *reinterpret_cast<const float4*>(
                    &Wih[(size_t)(e0 + row) * G4_ + n0 + c4 * 4]);
        }
        __syncthreads();

        #pragma unroll
        for (int kk = 0; kk < 16; kk++) {
            ulonglong2 a01 = *reinterpret_cast<ulonglong2*>(&As[kk][ty * 8]);
            ulonglong2 a23 = *reinterpret_cast<ulonglong2*>(&As[kk][ty * 8 + 4]);
            unsigned long long a2[4] = {a01.x, a01.y, a23.x, a23.y};
            float4 bv = *reinterpret_cast<float4*>(&Bs[kk][tx * 4]);
            unsigned long long bb[4] = {pk2(bv.x, bv.x), pk2(bv.y, bv.y),
                                        pk2(bv.z, bv.z), pk2(bv.w, bv.w)};
            #pragma unroll
            for (int i = 0; i < 4; i++)
                #pragma unroll
                for (int j = 0; j < 4; j++)
                    acc[i][j] = ffma2(a2[i], bb[j], acc[i][j]);
        }
        __syncthreads();
    }

    float4 b4 = *reinterpret_cast<const float4*>(&bias[n0 + tx * 4]);
    #pragma unroll
    for (int rp = 0; rp < 4; rp++) {
        float r0[4], r1[4];
        #pragma unroll
        for (int j = 0; j < 4; j++) upk2(acc[rp][j], r0[j], r1[j]);
        int m = m0 + ty * 8 + rp * 2;
        float4 o0 = make_float4(r0[0] + b4.x, r0[1] + b4.y, r0[2] + b4.z, r0[3] + b4.w);
        float4 o1 = make_float4(r1[0] + b4.x, r1[1] + b4.y, r1[2] + b4.z, r1[3] + b4.w);
        *reinterpret_cast<float4*>(&g_xproj[(size_t)m * G4_ + n0 + tx * 4]) = o0;
        *reinterpret_cast<float4*>(&g_xproj[(size_t)(m + 1) * G4_ + n0 + tx * 4]) = o1;
    }
}

// ---------------- Phase 2: persistent HMMA LSTM -----------------------------
// 128 blocks x 512 threads (16 warps). Block owns 32 W_hh cols (c = g*8 + j).
// z[64][32] = hhi@Whi + hlo@Whi + hhi@Wlo (hi/lo bf16 split, fp32 HMMA acc).
// Warp w: m-tile mt = w>>2 (16 batches), n-tile nt = w&3 (8 cols); K unsplit
// -> 4-reg accumulator, no reduction. W pre-converted into per-lane fragment
// order in smem (LDS.64, conflict-free). h staged per 128-k chunk ([b][k]
// bf16, stride 136 -> conflict-free A-frag LDS.32), double-buffered with
// register prefetch, 1 sync/chunk.
//
// SMEM map (dynamic, 210944 B):
//   [0,      65536)   Whi frags: [nt][gk(64)][lane][2 u32]
//   [65536, 131072)   Wlo frags
//   [131072,165888)   hbuf0: hhi[64][136]bf16 + hlo[64][136]bf16 (17408 each)
//   [165888,200704)   hbuf1
//   [200704,208896)   zf[64][32] f32
//   [208896,210944)   cs[512] f32
#define SMEM_BYTES_ 210944

__global__ __launch_bounds__(512, 1) void lstm_chunk(const float* __restrict__ Whh,
                                                     int s0) {
    extern __shared__ __align__(16) char smem[];
    float* zf = (float*)(smem + 200704);
    float* cs = (float*)(smem + 208896);

    const int tid  = threadIdx.x;
    const int wid  = tid >> 5;
    const int lane = tid & 31;
    const int u0   = blockIdx.x * UPB_;
    const int mt   = wid >> 2;                  // m-tile: batches mt*16..+16
    const int nt   = wid & 3;                   // n-tile: cols nt*8..+8

    // ---- convert W slice into fragment-ordered smem (once per launch) ----
    // slot = (nt, gk, lane): c = nt*8 + lane/4; k = gk*16 + (lane%4)*2 +{0,1,8,9}
    #pragma unroll
    for (int it = 0; it < 16; it++) {
        int slot = it * 512 + tid;              // 0..8191
        int ln = slot & 31, gk = (slot >> 5) & 63, ntc = slot >> 11;
        int c = ntc * 8 + (ln >> 2);
        int kb = gk * 16 + (ln & 3) * 2;
        const float* wp = Whh + (size_t)kb * G4_ + (c >> 3) * H_ + u0 + (c & 7);
        float w0 = wp[0], w1 = wp[G4_];
        float w8 = wp[(size_t)8 * G4_], w9 = wp[(size_t)9 * G4_];
        float h0 = __bfloat162float(__float2bfloat16(w0));
        float h1 = __bfloat162float(__float2bfloat16(w1));
        float h8 = __bfloat162float(__float2bfloat16(w8));
        float h9 = __bfloat162float(__float2bfloat16(w9));
        unsigned off = (unsigned)(ntc * 64 + gk) * 256 + ln * 8;
        *reinterpret_cast<uint2*>(smem + off) =
            make_uint2(pkbf_hi(w0, w1), pkbf_hi(w8, w9));
        *reinterpret_cast<uint2*>(smem + 65536 + off) =
            make_uint2(pkbf_hi(w0 - h0, w1 - h1), pkbf_hi(w8 - h8, w9 - h9));
    }
    // ---- block-private c state ----
    cs[tid] = g_cst[(tid >> 3) * H_ + u0 + (tid & 7)];
    __syncthreads();

    // staging: per thread 4 uint4. q0/q1 -> hi rows tid>>4, 32+(tid>>4);
    // q2/q3 -> lo same rows. col16 = tid&15.
    const int srw = tid >> 4;                   // 0..31
    const int sc16 = tid & 15;

    for (int ls = 0; ls < TCH_; ls++) {
        const int s = s0 + ls;
        const __nv_bfloat16* hbi = g_hbf_hi[s & 1];
        const __nv_bfloat16* hlo = g_hbf_lo[s & 1];
        __nv_bfloat16* nhi = g_hbf_hi[(s + 1) & 1];
        __nv_bfloat16* nlo = g_hbf_lo[(s + 1) & 1];
        const float* __restrict__ Xp = g_xproj + (size_t)ls * (B_ * G4_);

        float c0 = 0.f, c1 = 0.f, c2 = 0.f, c3 = 0.f;

        // prefetch chunk 0
        uint4 p0 = __ldcg(reinterpret_cast<const uint4*>(&hbi[srw * H_ + sc16 * 8]));
        uint4 p1 = __ldcg(reinterpret_cast<const uint4*>(&hbi[(32 + srw) * H_ + sc16 * 8]));
        uint4 p2 = __ldcg(reinterpret_cast<const uint4*>(&hlo[srw * H_ + sc16 * 8]));
        uint4 p3 = __ldcg(reinterpret_cast<const uint4*>(&hlo[(32 + srw) * H_ + sc16 * 8]));

        for (int ch = 0; ch < 8; ch++) {
            char* hb = smem + 131072 + (ch & 1) * 34816;
            // stage chunk ch: [b][k] bf16, row stride 272 B
            *reinterpret_cast<uint4*>(hb + srw * 272 + sc16 * 16) = p0;
            *reinterpret_cast<uint4*>(hb + (32 + srw) * 272 + sc16 * 16) = p1;
            *reinterpret_cast<uint4*>(hb + 17408 + srw * 272 + sc16 * 16) = p2;
            *reinterpret_cast<uint4*>(hb + 17408 + (32 + srw) * 272 + sc16 * 16) = p3;
            if (ch < 7) {
                int kb = (ch + 1) * 128;
                p0 = __ldcg(reinterpret_cast<const uint4*>(&hbi[srw * H_ + kb + sc16 * 8]));
                p1 = __ldcg(reinterpret_cast<const uint4*>(&hbi[(32 + srw) * H_ + kb + sc16 * 8]));
                p2 = __ldcg(reinterpret_cast<const uint4*>(&hlo[srw * H_ + kb + sc16 * 8]));
                p3 = __ldcg(reinterpret_cast<const uint4*>(&hlo[(32 + srw) * H_ + kb + sc16 * 8]));
            }
            __syncthreads();

            const unsigned* hhi32 = (const unsigned*)hb;
            const unsigned* hlo32 = (const unsigned*)(hb + 17408);
            const int rA = mt * 16 + (lane >> 2);
            const int wb0 = rA * 68 + (lane & 3);        // word index base
            #pragma unroll
            for (int ks = 0; ks < 8; ks++) {
                const int gk = ch * 8 + ks;
                const int wb = wb0 + ks * 8;
                unsigned ah0 = hhi32[wb],           ah1 = hhi32[wb + 8 * 68];
                unsigned ah2 = hhi32[wb + 4],       ah3 = hhi32[wb + 8 * 68 + 4];
                unsigned al0 = hlo32[wb],           al1 = hlo32[wb + 8 * 68];
                unsigned al2 = hlo32[wb + 4],       al3 = hlo32[wb + 8 * 68 + 4];
                uint2 bh = *reinterpret_cast<const uint2*>(
                    smem + (unsigned)(nt * 64 + gk) * 256 + lane * 8);
                uint2 bl = *reinterpret_cast<const uint2*>(
                    smem + 65536 + (unsigned)(nt * 64 + gk) * 256 + lane * 8);
                mma16816(c0, c1, c2, c3, ah0, ah1, ah2, ah3, bh.x, bh.y);
                mma16816(c0, c1, c2, c3, al0, al1, al2, al3, bh.x, bh.y);
                mma16816(c0, c1, c2, c3, ah0, ah1, ah2, ah3, bl.x, bl.y);
            }
            __syncthreads();
        }

        // ---- write z tile to smem: lane -> rows mt*16+l/4 (+8), cols 2 ----
        {
            int rz = mt * 16 + (lane >> 2);
            int cz = nt * 8 + (lane & 3) * 2;
            *reinterpret_cast<float2*>(&zf[rz * 32 + cz]) = make_float2(c0, c1);
            *reinterpret_cast<float2*>(&zf[(rz + 8) * 32 + cz]) = make_float2(c2, c3);
        }
        __syncthreads();

        // ---- gates: one cell per thread ----
        {
            int b = tid >> 3, j = tid & 7;
            const float* xa = &Xp[(size_t)b * G4_ + u0 + j];
            float zi  = zf[b * 32 + j]      + xa[0];
            float zff = zf[b * 32 + 8 + j]  + xa[H_];
            float zg  = zf[b * 32 + 16 + j] + xa[2 * H_];
            float zo  = zf[b * 32 + 24 + j] + xa[3 * H_];
            float ig = sigm(zi);
            float fg = sigm(zff);
            float gg = tanha(zg);
            float og = sigm(zo);
            float cn = fg * cs[tid] + ig * gg;
            cs[tid] = cn;
            float h = og * tanha(cn);
            __nv_bfloat16 bh = __float2bfloat16(h);
            nhi[b * H_ + u0 + j] = bh;
            nlo[b * H_ + u0 + j] = __float2bfloat16(h - __bfloat162float(bh));
            if (s == T_ - 1) g_hfin[b * H_ + u0 + j] = h;
        }

        // ---- grid-wide barrier (release arrival, acquire spin) ----
        __threadfence();
        __syncthreads();
        if (tid == 0) {
            asm volatile("red.release.gpu.global.add.u32 [%0], 1;"
                         :: "l"(&g_bar[s]) : "memory");
            unsigned v;
            do {
                asm volatile("ld.acquire.gpu.global.u32 %0, [%1];"
                             : "=r"(v) : "l"(&g_bar[s]) : "memory");
            } while (v < NBLK_);
        }
        __syncthreads();
    }

    // ---- persist c state ----
    g_cst[(tid >> 3) * H_ + u0 + (tid & 7)] = cs[tid];
}

// ------------------------------- output -------------------------------------
__global__ void write_out(float* __restrict__ out) {
    int i = blockIdx.x * blockDim.x + threadIdx.x;
    if (i < B_ * H_) {
        out[i] = g_hfin[i];
        out[B_ * H_ + i] = g_cst[i];
    }
}

extern "C" void kernel_launch(void* const* d_in, const int* in_sizes, int n_in,
                              void* d_out, int out_size) {
    (void)in_sizes; (void)n_in; (void)out_size;
    const int*   src  = (const int*)d_in[0];
    const float* emb  = (const float*)d_in[1];
    const float* Wih  = (const float*)d_in[2];
    const float* Whh  = (const float*)d_in[3];
    const float* bias = (const float*)d_in[4];
    float* out = (float*)d_out;

    cudaFuncSetAttribute(lstm_chunk, cudaFuncAttributeMaxDynamicSharedMemorySize,
                         SMEM_BYTES_);

    // Two init launches on purpose: shifts launch indices so ncu's "-s 5 -c 1"
    // window lands on lstm_chunk (launch #6). init_state is idempotent.
    init_state<<<(B_ * H_ + 255) / 256, 256>>>();
    init_state<<<(B_ * H_ + 255) / 256, 256>>>();
    for (int t0 = 0; t0 < T_; t0 += TCH_) {
        xproj_gemm<<<dim3(G4_ / 64, (TCH_ * B_) / 128), 256>>>(src, emb, Wih,
                                                               bias, t0);
        lstm_chunk<<<NBLK_, 512, SMEM_BYTES_>>>(Whh, t0);
    }
    write_out<<<(B_ * H_ + 255) / 256, 256>>>(out);
}

// round 15
// speedup vs baseline: 2.9103x; 1.1574x over previous
#include <cuda_runtime.h>
#include <cuda_bf16.h>
#include <math.h>

#define B_    64
#define T_    512
#define E_    512
#define H_    1024
#define V_    32000
#define G4_   4096   /* 4*H */
#define TCH_  128    /* time chunk (xproj scratch + persistent span) */
#define NBLK_ 128    /* persistent grid */
#define UPB_  8      /* hidden units per block */

// ---- global scratch (alloc-free rule: __device__ globals) ----
__device__ float g_xproj[(size_t)B_ * TCH_ * G4_];     // 128 MB chunk slab
__device__ __nv_bfloat16 g_emb_hi[(size_t)V_ * E_];    // bf16 emb table hi
__device__ __nv_bfloat16 g_emb_lo[(size_t)V_ * E_];    // bf16 emb table lo
__device__ __nv_bfloat16 g_wt_hi[(size_t)G4_ * E_];    // W_ih^T bf16 hi [N][K]
__device__ __nv_bfloat16 g_wt_lo[(size_t)G4_ * E_];    // W_ih^T bf16 lo
__device__ __nv_bfloat16 g_hbf_hi[2][B_ * H_];         // h bf16 hi, [B][H]
__device__ __nv_bfloat16 g_hbf_lo[2][B_ * H_];         // h bf16 lo
__device__ float g_hfin[B_ * H_];                      // final h fp32 [B][H]
__device__ float g_cst[B_ * H_];                       // c state [B][H]
__device__ unsigned g_bar[T_];                         // per-step arrivals

// ---------------- helpers ---------------------------------------------------
__device__ __forceinline__ float tanha(float x) {
    float y;
    asm("tanh.approx.f32 %0, %1;" : "=f"(y) : "f"(x));
    return y;
}
__device__ __forceinline__ float sigm(float x) {
    return __fdividef(1.f, 1.f + __expf(-x));
}
__device__ __forceinline__ unsigned pkbf_hi(float a, float b) {
    unsigned short x = __bfloat16_as_ushort(__float2bfloat16(a));
    unsigned short y = __bfloat16_as_ushort(__float2bfloat16(b));
    return (unsigned)x | ((unsigned)y << 16);
}

// mma.sync m16n8k16 bf16 (base sm_80+ instruction -> OK for plain sm_103)
__device__ __forceinline__ void mma16816(float& c0, float& c1, float& c2, float& c3,
                                         unsigned a0, unsigned a1, unsigned a2,
                                         unsigned a3, unsigned b0, unsigned b1) {
    asm volatile(
        "mma.sync.aligned.m16n8k16.row.col.f32.bf16.bf16.f32 "
        "{%0,%1,%2,%3},{%4,%5,%6,%7},{%8,%9},{%0,%1,%2,%3};"
        : "+f"(c0), "+f"(c1), "+f"(c2), "+f"(c3)
        : "r"(a0), "r"(a1), "r"(a2), "r"(a3), "r"(b0), "r"(b1));
}

// ---------------------------- init ------------------------------------------
__global__ void init_state() {
    int i = blockIdx.x * blockDim.x + threadIdx.x;
    if (i < B_ * H_) {
        g_hbf_hi[0][i] = __ushort_as_bfloat16(0);
        g_hbf_lo[0][i] = __ushort_as_bfloat16(0);
        g_cst[i] = 0.f;
    }
    if (i < T_) g_bar[i] = 0u;
}

// ---------------- prep: bf16 hi/lo tables (once per run) --------------------
__global__ void prep_bf16(const float* __restrict__ emb,
                          const float* __restrict__ Wih) {
    int i = blockIdx.x * blockDim.x + threadIdx.x;
    if (i < V_ * E_) {
        float v = emb[i];
        __nv_bfloat16 h = __float2bfloat16(v);
        g_emb_hi[i] = h;
        g_emb_lo[i] = __float2bfloat16(v - __bfloat162float(h));
    }
    if (i < E_ * G4_) {
        // i = k*4096 + n (coalesced read); write transposed [n][k]
        int k = i >> 12, n = i & 4095;
        float v = Wih[i];
        __nv_bfloat16 h = __float2bfloat16(v);
        g_wt_hi[(size_t)n * E_ + k] = h;
        g_wt_lo[(size_t)n * E_ + k] = __float2bfloat16(v - __bfloat162float(h));
    }
}

// ---------------- Phase 1: HMMA Xproj chunk ---------------------------------
// C[8192, 4096] = emb[src] @ W_ih + bias over one 128-step time chunk,
// bf16 hi/lo 3-pass (Ah*Bh + Al*Bh + Ah*Bl), fp32 accumulate.
// Block = 128x64 tile, 8 warps (4m x 2n), warp tile 32x32 (2 m-frags x
// 4 n-frags), K-chunks of 32. Fragment layout identical to lstm_chunk's
// (proven): A row-major [m][k], B from transposed W [n][k].
__global__ __launch_bounds__(256) void xproj_hmma(const int* __restrict__ src,
                                                  const float* __restrict__ bias,
                                                  int t0) {
    __shared__ __align__(16) __nv_bfloat16 Ah[128][40], Al[128][40];
    __shared__ __align__(16) __nv_bfloat16 Bh[64][40],  Bl[64][40];
    __shared__ int srow[128];

    const int tid = threadIdx.x;
    const int wid = tid >> 5, lane = tid & 31;
    const int m0 = blockIdx.y * 128;
    const int n0 = blockIdx.x * 64;
    const int wm = wid >> 1, wn = wid & 1;

    if (tid < 128) {
        int m = m0 + tid;
        srow[tid] = src[(m & 63) * T_ + t0 + (m >> 6)];
    }

    float acc[2][4][4];
    #pragma unroll
    for (int a = 0; a < 2; a++)
        #pragma unroll
        for (int b = 0; b < 4; b++)
            #pragma unroll
            for (int c = 0; c < 4; c++) acc[a][b][c] = 0.f;

    for (int ch = 0; ch < 16; ch++) {
        const int k0 = ch * 32;
        __syncthreads();          // staging vs prior frag reads (and srow @ch0)
        #pragma unroll
        for (int i = 0; i < 2; i++) {
            int idx = tid + i * 256;            // 0..511
            int r = idx >> 2, q = idx & 3;
            const size_t go = (size_t)srow[r] * E_ + k0 + q * 8;
            *reinterpret_cast<uint4*>(&Ah[r][q * 8]) =
                *reinterpret_cast<const uint4*>(&g_emb_hi[go]);
            *reinterpret_cast<uint4*>(&Al[r][q * 8]) =
                *reinterpret_cast<const uint4*>(&g_emb_lo[go]);
        }
        {
            int r = tid >> 2, q = tid & 3;      // r 0..63
            const size_t go = (size_t)(n0 + r) * E_ + k0 + q * 8;
            *reinterpret_cast<uint4*>(&Bh[r][q * 8]) =
                *reinterpret_cast<const uint4*>(&g_wt_hi[go]);
            *reinterpret_cast<uint4*>(&Bl[r][q * 8]) =
                *reinterpret_cast<const uint4*>(&g_wt_lo[go]);
        }
        __syncthreads();

        #pragma unroll
        for (int ks = 0; ks < 2; ks++) {
            const int kc = ks * 16 + (lane & 3) * 2;
            unsigned ah[2][4], al[2][4];
            #pragma unroll
            for (int mf = 0; mf < 2; mf++) {
                int rm = wm * 32 + mf * 16 + (lane >> 2);
                ah[mf][0] = *reinterpret_cast<const unsigned*>(&Ah[rm][kc]);
                ah[mf][1] = *reinterpret_cast<const unsigned*>(&Ah[rm + 8][kc]);
                ah[mf][2] = *reinterpret_cast<const unsigned*>(&Ah[rm][kc + 8]);
                ah[mf][3] = *reinterpret_cast<const unsigned*>(&Ah[rm + 8][kc + 8]);
                al[mf][0] = *reinterpret_cast<const unsigned*>(&Al[rm][kc]);
                al[mf][1] = *reinterpret_cast<const unsigned*>(&Al[rm + 8][kc]);
                al[mf][2] = *reinterpret_cast<const unsigned*>(&Al[rm][kc + 8]);
                al[mf][3] = *reinterpret_cast<const unsigned*>(&Al[rm + 8][kc + 8]);
            }
            #pragma unroll
            for (int nf = 0; nf < 4; nf++) {
                int cn = wn * 32 + nf * 8 + (lane >> 2);
                unsigned bh0 = *reinterpret_cast<const unsigned*>(&Bh[cn][kc]);
                unsigned bh1 = *reinterpret_cast<const unsigned*>(&Bh[cn][kc + 8]);
                unsigned bl0 = *reinterpret_cast<const unsigned*>(&Bl[cn][kc]);
                unsigned bl1 = *reinterpret_cast<const unsigned*>(&Bl[cn][kc + 8]);
                #pragma unroll
                for (int mf = 0; mf < 2; mf++) {
                    mma16816(acc[mf][nf][0], acc[mf][nf][1],
                             acc[mf][nf][2], acc[mf][nf][3],
                             ah[mf][0], ah[mf][1], ah[mf][2], ah[mf][3],
                             bh0, bh1);
                    mma16816(acc[mf][nf][0], acc[mf][nf][1],
                             acc[mf][nf][2], acc[mf][nf][3],
                             al[mf][0], al[mf][1], al[mf][2], al[mf][3],
                             bh0, bh1);
                    mma16816(acc[mf][nf][0], acc[mf][nf][1],
                             acc[mf][nf][2], acc[mf][nf][3],
                             ah[mf][0], ah[mf][1], ah[mf][2], ah[mf][3],
                             bl0, bl1);
                }
            }
        }
    }

    // epilogue: += bias, write fp32
    #pragma unroll
    for (int nf = 0; nf < 4; nf++) {
        int n = n0 + wn * 32 + nf * 8 + (lane & 3) * 2;
        float2 bv = *reinterpret_cast<const float2*>(&bias[n]);
        #pragma unroll
        for (int mf = 0; mf < 2; mf++) {
            int m = m0 + wm * 32 + mf * 16 + (lane >> 2);
            *reinterpret_cast<float2*>(&g_xproj[(size_t)m * G4_ + n]) =
                make_float2(acc[mf][nf][0] + bv.x, acc[mf][nf][1] + bv.y);
            *reinterpret_cast<float2*>(&g_xproj[(size_t)(m + 8) * G4_ + n]) =
                make_float2(acc[mf][nf][2] + bv.x, acc[mf][nf][3] + bv.y);
        }
    }
}

// ---------------- Phase 2: persistent HMMA LSTM (unchanged from R14) --------
// SMEM map (dynamic, 210944 B):
//   [0,      65536)   Whi frags: [nt][gk(64)][lane][2 u32]
//   [65536, 131072)   Wlo frags
//   [131072,165888)   hbuf0: hhi[64][136]bf16 + hlo[64][136]bf16
//   [165888,200704)   hbuf1
//   [200704,208896)   zf[64][32] f32
//   [208896,210944)   cs[512] f32
#define SMEM_BYTES_ 210944

__global__ __launch_bounds__(512, 1) void lstm_chunk(const float* __restrict__ Whh,
                                                     int s0) {
    extern __shared__ __align__(16) char smem[];
    float* zf = (float*)(smem + 200704);
    float* cs = (float*)(smem + 208896);

    const int tid  = threadIdx.x;
    const int wid  = tid >> 5;
    const int lane = tid & 31;
    const int u0   = blockIdx.x * UPB_;
    const int mt   = wid >> 2;
    const int nt   = wid & 3;

    #pragma unroll
    for (int it = 0; it < 16; it++) {
        int slot = it * 512 + tid;
        int ln = slot & 31, gk = (slot >> 5) & 63, ntc = slot >> 11;
        int c = ntc * 8 + (ln >> 2);
        int kb = gk * 16 + (ln & 3) * 2;
        const float* wp = Whh + (size_t)kb * G4_ + (c >> 3) * H_ + u0 + (c & 7);
        float w0 = wp[0], w1 = wp[G4_];
        float w8 = wp[(size_t)8 * G4_], w9 = wp[(size_t)9 * G4_];
        float h0 = __bfloat162float(__float2bfloat16(w0));
        float h1 = __bfloat162float(__float2bfloat16(w1));
        float h8 = __bfloat162float(__float2bfloat16(w8));
        float h9 = __bfloat162float(__float2bfloat16(w9));
        unsigned off = (unsigned)(ntc * 64 + gk) * 256 + ln * 8;
        *reinterpret_cast<uint2*>(smem + off) =
            make_uint2(pkbf_hi(w0, w1), pkbf_hi(w8, w9));
        *reinterpret_cast<uint2*>(smem + 65536 + off) =
            make_uint2(pkbf_hi(w0 - h0, w1 - h1), pkbf_hi(w8 - h8, w9 - h9));
    }
    cs[tid] = g_cst[(tid >> 3) * H_ + u0 + (tid & 7)];
    __syncthreads();

    const int srw = tid >> 4;
    const int sc16 = tid & 15;

    for (int ls = 0; ls < TCH_; ls++) {
        const int s = s0 + ls;
        const __nv_bfloat16* hbi = g_hbf_hi[s & 1];
        const __nv_bfloat16* hlo = g_hbf_lo[s & 1];
        __nv_bfloat16* nhi = g_hbf_hi[(s + 1) & 1];
        __nv_bfloat16* nlo = g_hbf_lo[(s + 1) & 1];
        const float* __restrict__ Xp = g_xproj + (size_t)ls * (B_ * G4_);

        float c0 = 0.f, c1 = 0.f, c2 = 0.f, c3 = 0.f;

        uint4 p0 = __ldcg(reinterpret_cast<const uint4*>(&hbi[srw * H_ + sc16 * 8]));
        uint4 p1 = __ldcg(reinterpret_cast<const uint4*>(&hbi[(32 + srw) * H_ + sc16 * 8]));
        uint4 p2 = __ldcg(reinterpret_cast<const uint4*>(&hlo[srw * H_ + sc16 * 8]));
        uint4 p3 = __ldcg(reinterpret_cast<const uint4*>(&hlo[(32 + srw) * H_ + sc16 * 8]));

        for (int ch = 0; ch < 8; ch++) {
            char* hb = smem + 131072 + (ch & 1) * 34816;
            *reinterpret_cast<uint4*>(hb + srw * 272 + sc16 * 16) = p0;
            *reinterpret_cast<uint4*>(hb + (32 + srw) * 272 + sc16 * 16) = p1;
            *reinterpret_cast<uint4*>(hb + 17408 + srw * 272 + sc16 * 16) = p2;
            *reinterpret_cast<uint4*>(hb + 17408 + (32 + srw) * 272 + sc16 * 16) = p3;
            if (ch < 7) {
                int kb = (ch + 1) * 128;
                p0 = __ldcg(reinterpret_cast<const uint4*>(&hbi[srw * H_ + kb + sc16 * 8]));
                p1 = __ldcg(reinterpret_cast<const uint4*>(&hbi[(32 + srw) * H_ + kb + sc16 * 8]));
                p2 = __ldcg(reinterpret_cast<const uint4*>(&hlo[srw * H_ + kb + sc16 * 8]));
                p3 = __ldcg(reinterpret_cast<const uint4*>(&hlo[(32 + srw) * H_ + kb + sc16 * 8]));
            }
            __syncthreads();

            const unsigned* hhi32 = (const unsigned*)hb;
            const unsigned* hlo32 = (const unsigned*)(hb + 17408);
            const int rA = mt * 16 + (lane >> 2);
            const int wb0 = rA * 68 + (lane & 3);
            #pragma unroll
            for (int ks = 0; ks < 8; ks++) {
                const int gk = ch * 8 + ks;
                const int wb = wb0 + ks * 8;
                unsigned ah0 = hhi32[wb],     ah1 = hhi32[wb + 8 * 68];
                unsigned ah2 = hhi32[wb + 4], ah3 = hhi32[wb + 8 * 68 + 4];
                unsigned al0 = hlo32[wb],     al1 = hlo32[wb + 8 * 68];
                unsigned al2 = hlo32[wb + 4], al3 = hlo32[wb + 8 * 68 + 4];
                uint2 bh = *reinterpret_cast<const uint2*>(
                    smem + (unsigned)(nt * 64 + gk) * 256 + lane * 8);
                uint2 bl = *reinterpret_cast<const uint2*>(
                    smem + 65536 + (unsigned)(nt * 64 + gk) * 256 + lane * 8);
                mma16816(c0, c1, c2, c3, ah0, ah1, ah2, ah3, bh.x, bh.y);
                mma16816(c0, c1, c2, c3, al0, al1, al2, al3, bh.x, bh.y);
                mma16816(c0, c1, c2, c3, ah0, ah1, ah2, ah3, bl.x, bl.y);
            }
            __syncthreads();
        }

        {
            int rz = mt * 16 + (lane >> 2);
            int cz = nt * 8 + (lane & 3) * 2;
            *reinterpret_cast<float2*>(&zf[rz * 32 + cz]) = make_float2(c0, c1);
            *reinterpret_cast<float2*>(&zf[(rz + 8) * 32 + cz]) = make_float2(c2, c3);
        }
        __syncthreads();

        {
            int b = tid >> 3, j = tid & 7;
            const float* xa = &Xp[(size_t)b * G4_ + u0 + j];
            float zi  = zf[b * 32 + j]      + xa[0];
            float zff = zf[b * 32 + 8 + j]  + xa[H_];
            float zg  = zf[b * 32 + 16 + j] + xa[2 * H_];
            float zo  = zf[b * 32 + 24 + j] + xa[3 * H_];
            float ig = sigm(zi);
            float fg = sigm(zff);
            float gg = tanha(zg);
            float og = sigm(zo);
            float cn = fg * cs[tid] + ig * gg;
            cs[tid] = cn;
            float h = og * tanha(cn);
            __nv_bfloat16 bh = __float2bfloat16(h);
            nhi[b * H_ + u0 + j] = bh;
            nlo[b * H_ + u0 + j] = __float2bfloat16(h - __bfloat162float(bh));
            if (s == T_ - 1) g_hfin[b * H_ + u0 + j] = h;
        }

        __threadfence();
        __syncthreads();
        if (tid == 0) {
            asm volatile("red.release.gpu.global.add.u32 [%0], 1;"
                         :: "l"(&g_bar[s]) : "memory");
            unsigned v;
            do {
                asm volatile("ld.acquire.gpu.global.u32 %0, [%1];"
                             : "=r"(v) : "l"(&g_bar[s]) : "memory");
            } while (v < NBLK_);
        }
        __syncthreads();
    }

    g_cst[(tid >> 3) * H_ + u0 + (tid & 7)] = cs[tid];
}

// ------------------------------- output -------------------------------------
__global__ void write_out(float* __restrict__ out) {
    int i = blockIdx.x * blockDim.x + threadIdx.x;
    if (i < B_ * H_) {
        out[i] = g_hfin[i];
        out[B_ * H_ + i] = g_cst[i];
    }
}

extern "C" void kernel_launch(void* const* d_in, const int* in_sizes, int n_in,
                              void* d_out, int out_size) {
    (void)in_sizes; (void)n_in; (void)out_size;
    const int*   src  = (const int*)d_in[0];
    const float* emb  = (const float*)d_in[1];
    const float* Wih  = (const float*)d_in[2];
    const float* Whh  = (const float*)d_in[3];
    const float* bias = (const float*)d_in[4];
    float* out = (float*)d_out;

    cudaFuncSetAttribute(lstm_chunk, cudaFuncAttributeMaxDynamicSharedMemorySize,
                         SMEM_BYTES_);

    // Two init launches on purpose: shifts launch indices so ncu's "-s 5 -c 1"
    // window lands on xproj_hmma (launch #5). init_state is idempotent.
    init_state<<<(B_ * H_ + 255) / 256, 256>>>();
    init_state<<<(B_ * H_ + 255) / 256, 256>>>();
    prep_bf16<<<(V_ * E_ + 255) / 256, 256>>>(emb, Wih);
    for (int t0 = 0; t0 < T_; t0 += TCH_) {
        xproj_hmma<<<dim3(G4_ / 64, (TCH_ * B_) / 128), 256>>>(src, bias, t0);
        lstm_chunk<<<NBLK_, 512, SMEM_BYTES_>>>(Whh, t0);
    }
    write_out<<<(B_ * H_ + 255) / 256, 256>>>(out);
}

// round 16
// speedup vs baseline: 3.3638x; 1.1558x over previous
#include <cuda_runtime.h>
#include <cuda_bf16.h>
#include <math.h>

#define B_    64
#define T_    512
#define E_    512
#define H_    1024
#define V_    32000
#define G4_   4096   /* 4*H */
#define TCH_  128    /* time chunk (xproj scratch + persistent span) */
#define NBLK_ 128    /* persistent grid */
#define UPB_  8      /* hidden units per block */

// ---- global scratch (alloc-free rule: __device__ globals) ----
__device__ float g_xproj[(size_t)B_ * TCH_ * G4_];     // 128 MB chunk slab
__device__ __nv_bfloat16 g_emb_hi[(size_t)V_ * E_];    // bf16 emb table hi
__device__ __nv_bfloat16 g_emb_lo[(size_t)V_ * E_];    // bf16 emb table lo
__device__ __nv_bfloat16 g_wt_hi[(size_t)G4_ * E_];    // W_ih^T bf16 hi [N][K]
__device__ __nv_bfloat16 g_wt_lo[(size_t)G4_ * E_];    // W_ih^T bf16 lo
__device__ __nv_bfloat16 g_hbf_hi[2][B_ * H_];         // h bf16 hi, [B][H]
__device__ __nv_bfloat16 g_hbf_lo[2][B_ * H_];         // h bf16 lo
__device__ float g_hfin[B_ * H_];                      // final h fp32 [B][H]
__device__ float g_cst[B_ * H_];                       // c state [B][H]
__device__ unsigned g_bar[T_];                         // per-step arrivals

// ---------------- helpers ---------------------------------------------------
__device__ __forceinline__ float tanha(float x) {
    float y;
    asm("tanh.approx.f32 %0, %1;" : "=f"(y) : "f"(x));
    return y;
}
__device__ __forceinline__ float sigm(float x) {
    return __fdividef(1.f, 1.f + __expf(-x));
}
__device__ __forceinline__ unsigned pkbf_hi(float a, float b) {
    unsigned short x = __bfloat16_as_ushort(__float2bfloat16(a));
    unsigned short y = __bfloat16_as_ushort(__float2bfloat16(b));
    return (unsigned)x | ((unsigned)y << 16);
}

// mma.sync m16n8k16 bf16 (base sm_80+ instruction)
__device__ __forceinline__ void mma16816(float& c0, float& c1, float& c2, float& c3,
                                         unsigned a0, unsigned a1, unsigned a2,
                                         unsigned a3, unsigned b0, unsigned b1) {
    asm volatile(
        "mma.sync.aligned.m16n8k16.row.col.f32.bf16.bf16.f32 "
        "{%0,%1,%2,%3},{%4,%5,%6,%7},{%8,%9},{%0,%1,%2,%3};"
        : "+f"(c0), "+f"(c1), "+f"(c2), "+f"(c3)
        : "r"(a0), "r"(a1), "r"(a2), "r"(a3), "r"(b0), "r"(b1));
}

// ---------------------------- init ------------------------------------------
__global__ void init_state() {
    int i = blockIdx.x * blockDim.x + threadIdx.x;
    if (i < B_ * H_) {
        g_hbf_hi[0][i] = __ushort_as_bfloat16(0);
        g_hbf_lo[0][i] = __ushort_as_bfloat16(0);
        g_cst[i] = 0.f;
    }
    if (i < T_) g_bar[i] = 0u;
}

// ---------------- prep: bf16 hi/lo tables (once per run) --------------------
__global__ void prep_bf16(const float* __restrict__ emb,
                          const float* __restrict__ Wih) {
    int i = blockIdx.x * blockDim.x + threadIdx.x;
    if (i < V_ * E_) {
        float v = emb[i];
        __nv_bfloat16 h = __float2bfloat16(v);
        g_emb_hi[i] = h;
        g_emb_lo[i] = __float2bfloat16(v - __bfloat162float(h));
    }
    if (i < E_ * G4_) {
        int k = i >> 12, n = i & 4095;
        float v = Wih[i];
        __nv_bfloat16 h = __float2bfloat16(v);
        g_wt_hi[(size_t)n * E_ + k] = h;
        g_wt_lo[(size_t)n * E_ + k] = __float2bfloat16(v - __bfloat162float(h));
    }
}

// ---------------- Phase 1: HMMA Xproj chunk (unchanged from R15) ------------
__global__ __launch_bounds__(256) void xproj_hmma(const int* __restrict__ src,
                                                  const float* __restrict__ bias,
                                                  int t0) {
    __shared__ __align__(16) __nv_bfloat16 Ah[128][40], Al[128][40];
    __shared__ __align__(16) __nv_bfloat16 Bh[64][40],  Bl[64][40];
    __shared__ int srow[128];

    const int tid = threadIdx.x;
    const int wid = tid >> 5, lane = tid & 31;
    const int m0 = blockIdx.y * 128;
    const int n0 = blockIdx.x * 64;
    const int wm = wid >> 1, wn = wid & 1;

    if (tid < 128) {
        int m = m0 + tid;
        srow[tid] = src[(m & 63) * T_ + t0 + (m >> 6)];
    }

    float acc[2][4][4];
    #pragma unroll
    for (int a = 0; a < 2; a++)
        #pragma unroll
        for (int b = 0; b < 4; b++)
            #pragma unroll
            for (int c = 0; c < 4; c++) acc[a][b][c] = 0.f;

    for (int ch = 0; ch < 16; ch++) {
        const int k0 = ch * 32;
        __syncthreads();
        #pragma unroll
        for (int i = 0; i < 2; i++) {
            int idx = tid + i * 256;
            int r = idx >> 2, q = idx & 3;
            const size_t go = (size_t)srow[r] * E_ + k0 + q * 8;
            *reinterpret_cast<uint4*>(&Ah[r][q * 8]) =
                *reinterpret_cast<const uint4*>(&g_emb_hi[go]);
            *reinterpret_cast<uint4*>(&Al[r][q * 8]) =
                *reinterpret_cast<const uint4*>(&g_emb_lo[go]);
        }
        {
            int r = tid >> 2, q = tid & 3;
            const size_t go = (size_t)(n0 + r) * E_ + k0 + q * 8;
            *reinterpret_cast<uint4*>(&Bh[r][q * 8]) =
                *reinterpret_cast<const uint4*>(&g_wt_hi[go]);
            *reinterpret_cast<uint4*>(&Bl[r][q * 8]) =
                *reinterpret_cast<const uint4*>(&g_wt_lo[go]);
        }
        __syncthreads();

        #pragma unroll
        for (int ks = 0; ks < 2; ks++) {
            const int kc = ks * 16 + (lane & 3) * 2;
            unsigned ah[2][4], al[2][4];
            #pragma unroll
            for (int mf = 0; mf < 2; mf++) {
                int rm = wm * 32 + mf * 16 + (lane >> 2);
                ah[mf][0] = *reinterpret_cast<const unsigned*>(&Ah[rm][kc]);
                ah[mf][1] = *reinterpret_cast<const unsigned*>(&Ah[rm + 8][kc]);
                ah[mf][2] = *reinterpret_cast<const unsigned*>(&Ah[rm][kc + 8]);
                ah[mf][3] = *reinterpret_cast<const unsigned*>(&Ah[rm + 8][kc + 8]);
                al[mf][0] = *reinterpret_cast<const unsigned*>(&Al[rm][kc]);
                al[mf][1] = *reinterpret_cast<const unsigned*>(&Al[rm + 8][kc]);
                al[mf][2] = *reinterpret_cast<const unsigned*>(&Al[rm][kc + 8]);
                al[mf][3] = *reinterpret_cast<const unsigned*>(&Al[rm + 8][kc + 8]);
            }
            #pragma unroll
            for (int nf = 0; nf < 4; nf++) {
                int cn = wn * 32 + nf * 8 + (lane >> 2);
                unsigned bh0 = *reinterpret_cast<const unsigned*>(&Bh[cn][kc]);
                unsigned bh1 = *reinterpret_cast<const unsigned*>(&Bh[cn][kc + 8]);
                unsigned bl0 = *reinterpret_cast<const unsigned*>(&Bl[cn][kc]);
                unsigned bl1 = *reinterpret_cast<const unsigned*>(&Bl[cn][kc + 8]);
                #pragma unroll
                for (int mf = 0; mf < 2; mf++) {
                    mma16816(acc[mf][nf][0], acc[mf][nf][1],
                             acc[mf][nf][2], acc[mf][nf][3],
                             ah[mf][0], ah[mf][1], ah[mf][2], ah[mf][3],
                             bh0, bh1);
                    mma16816(acc[mf][nf][0], acc[mf][nf][1],
                             acc[mf][nf][2], acc[mf][nf][3],
                             al[mf][0], al[mf][1], al[mf][2], al[mf][3],
                             bh0, bh1);
                    mma16816(acc[mf][nf][0], acc[mf][nf][1],
                             acc[mf][nf][2], acc[mf][nf][3],
                             ah[mf][0], ah[mf][1], ah[mf][2], ah[mf][3],
                             bl0, bl1);
                }
            }
        }
    }

    #pragma unroll
    for (int nf = 0; nf < 4; nf++) {
        int n = n0 + wn * 32 + nf * 8 + (lane & 3) * 2;
        float2 bv = *reinterpret_cast<const float2*>(&bias[n]);
        #pragma unroll
        for (int mf = 0; mf < 2; mf++) {
            int m = m0 + wm * 32 + mf * 16 + (lane >> 2);
            *reinterpret_cast<float2*>(&g_xproj[(size_t)m * G4_ + n]) =
                make_float2(acc[mf][nf][0] + bv.x, acc[mf][nf][1] + bv.y);
            *reinterpret_cast<float2*>(&g_xproj[(size_t)(m + 8) * G4_ + n]) =
                make_float2(acc[mf][nf][2] + bv.x, acc[mf][nf][3] + bv.y);
        }
    }
}

// ---------------- Phase 2: persistent HMMA LSTM, retiled --------------------
// 128 blocks x 512 threads (16 warps). Warp w: mt = w>>2 (16 batches),
// kq = w&3 (16-k slice within each staged 64-k chunk); warp tile m16 x n32
// (all 4 n-frags -> A-frags reused 4x, 4 independent acc chains).
// 16 chunks/step, double-buffered, 1 sync/chunk. Partials zs[4][64][33],
// reduced by the gate threads (c-state in registers). Xproj prefetched to
// smem at step start.
//
// SMEM map (dynamic, 209920 B):
//   [0,      65536)   Whi frags: [nf][gk(64)][lane][2 u32]
//   [65536, 131072)   Wlo frags
//   [131072,167936)   hbuf: 2 x { hi[64][72]bf16 (9216B), lo same } = 2x18432
//   [167936,201728)   zs[4][64][33] f32 partials
//   [201728,209920)   xs[64][32] f32 (Xproj slab)
#define SMEM_BYTES_ 209920

__global__ __launch_bounds__(512, 1) void lstm_chunk(const float* __restrict__ Whh,
                                                     int s0) {
    extern __shared__ __align__(16) char smem[];
    float* zs = (float*)(smem + 167936);
    float* xs = (float*)(smem + 201728);

    const int tid  = threadIdx.x;
    const int wid  = tid >> 5;
    const int lane = tid & 31;
    const int u0   = blockIdx.x * UPB_;
    const int mt   = wid >> 2;                  // m-tile (16 batches)
    const int kq   = wid & 3;                   // k-slice within chunk
    const int ln3  = lane & 3;
    const int rm0  = mt * 16 + (lane >> 2);     // A-frag row (batch)

    // ---- convert W slice into fragment-ordered smem (once per launch) ----
    #pragma unroll
    for (int it = 0; it < 16; it++) {
        int slot = it * 512 + tid;
        int ln = slot & 31, gk = (slot >> 5) & 63, ntc = slot >> 11;
        int c = ntc * 8 + (ln >> 2);
        int kb = gk * 16 + (ln & 3) * 2;
        const float* wp = Whh + (size_t)kb * G4_ + (c >> 3) * H_ + u0 + (c & 7);
        float w0 = wp[0], w1 = wp[G4_];
        float w8 = wp[(size_t)8 * G4_], w9 = wp[(size_t)9 * G4_];
        float h0 = __bfloat162float(__float2bfloat16(w0));
        float h1 = __bfloat162float(__float2bfloat16(w1));
        float h8 = __bfloat162float(__float2bfloat16(w8));
        float h9 = __bfloat162float(__float2bfloat16(w9));
        unsigned off = (unsigned)(ntc * 64 + gk) * 256 + ln * 8;
        *reinterpret_cast<uint2*>(smem + off) =
            make_uint2(pkbf_hi(w0, w1), pkbf_hi(w8, w9));
        *reinterpret_cast<uint2*>(smem + 65536 + off) =
            make_uint2(pkbf_hi(w0 - h0, w1 - h1), pkbf_hi(w8 - h8, w9 - h9));
    }
    // ---- c state in registers: thread owns cell (b = tid>>3, j = tid&7) ----
    const int gb = tid >> 3, gj = tid & 7;
    float creg = g_cst[gb * H_ + u0 + gj];
    __syncthreads();

    // staging map: thread stages hi+lo 8-k group: b = tid>>3, k8 = tid&7
    const int sb = tid >> 3, sk8 = tid & 7;

    for (int ls = 0; ls < TCH_; ls++) {
        const int s = s0 + ls;
        const __nv_bfloat16* hbi = g_hbf_hi[s & 1];
        const __nv_bfloat16* hlo = g_hbf_lo[s & 1];
        __nv_bfloat16* nhi = g_hbf_hi[(s + 1) & 1];
        __nv_bfloat16* nlo = g_hbf_lo[(s + 1) & 1];
        const float* __restrict__ Xp = g_xproj + (size_t)ls * (B_ * G4_);

        // ---- Xproj slab prefetch into xs (consumed at step end) ----
        {
            int seg = tid >> 1, o = (tid & 1) * 4;
            int b = seg >> 2, g = seg & 3;
            float4 xv = __ldg(reinterpret_cast<const float4*>(
                &Xp[(size_t)b * G4_ + g * H_ + u0 + o]));
            *reinterpret_cast<float4*>(&xs[b * 32 + g * 8 + o]) = xv;
        }

        float acc[4][4];
        #pragma unroll
        for (int a = 0; a < 4; a++)
            #pragma unroll
            for (int c = 0; c < 4; c++) acc[a][c] = 0.f;

        // ---- stage chunk 0, prefetch chunk 1 ----
        uint4 ph = __ldcg(reinterpret_cast<const uint4*>(&hbi[sb * H_ + sk8 * 8]));
        uint4 pl = __ldcg(reinterpret_cast<const uint4*>(&hlo[sb * H_ + sk8 * 8]));
        *reinterpret_cast<uint4*>(smem + 131072 + sb * 144 + sk8 * 16) = ph;
        *reinterpret_cast<uint4*>(smem + 131072 + 9216 + sb * 144 + sk8 * 16) = pl;
        ph = __ldcg(reinterpret_cast<const uint4*>(&hbi[sb * H_ + 64 + sk8 * 8]));
        pl = __ldcg(reinterpret_cast<const uint4*>(&hlo[sb * H_ + 64 + sk8 * 8]));
        __syncthreads();

        for (int ch = 0; ch < 16; ch++) {
            // store prefetched chunk ch+1 into the buffer NOT being read
            if (ch < 15) {
                char* nb = smem + 131072 + ((ch + 1) & 1) * 18432;
                *reinterpret_cast<uint4*>(nb + sb * 144 + sk8 * 16) = ph;
                *reinterpret_cast<uint4*>(nb + 9216 + sb * 144 + sk8 * 16) = pl;
            }
            if (ch < 14) {
                int kb = (ch + 2) * 64;
                ph = __ldcg(reinterpret_cast<const uint4*>(&hbi[sb * H_ + kb + sk8 * 8]));
                pl = __ldcg(reinterpret_cast<const uint4*>(&hlo[sb * H_ + kb + sk8 * 8]));
            }
            // MMA from current buffer
            const char* cb = smem + 131072 + (ch & 1) * 18432;
            const unsigned* Hh = (const unsigned*)cb;
            const unsigned* Hl = (const unsigned*)(cb + 9216);
            const int wbase = rm0 * 36 + kq * 8 + ln3;
            unsigned ah0 = Hh[wbase],       ah1 = Hh[wbase + 288];
            unsigned ah2 = Hh[wbase + 4],   ah3 = Hh[wbase + 292];
            unsigned al0 = Hl[wbase],       al1 = Hl[wbase + 288];
            unsigned al2 = Hl[wbase + 4],   al3 = Hl[wbase + 292];
            const int gk = ch * 4 + kq;
            #pragma unroll
            for (int nf = 0; nf < 4; nf++) {
                uint2 bh = *reinterpret_cast<const uint2*>(
                    smem + (unsigned)(nf * 64 + gk) * 256 + lane * 8);
                uint2 bl = *reinterpret_cast<const uint2*>(
                    smem + 65536 + (unsigned)(nf * 64 + gk) * 256 + lane * 8);
                mma16816(acc[nf][0], acc[nf][1], acc[nf][2], acc[nf][3],
                         ah0, ah1, ah2, ah3, bh.x, bh.y);
                mma16816(acc[nf][0], acc[nf][1], acc[nf][2], acc[nf][3],
                         al0, al1, al2, al3, bh.x, bh.y);
                mma16816(acc[nf][0], acc[nf][1], acc[nf][2], acc[nf][3],
                         ah0, ah1, ah2, ah3, bl.x, bl.y);
            }
            __syncthreads();
        }

        // ---- write k-slice partials: zs[kq][row][col], row stride 33 ----
        #pragma unroll
        for (int nf = 0; nf < 4; nf++) {
            int rz = mt * 16 + (lane >> 2);
            int cz = nf * 8 + ln3 * 2;
            float* zp = zs + kq * 2112 + rz * 33 + cz;
            zp[0] = acc[nf][0];
            zp[1] = acc[nf][1];
            zp[264] = acc[nf][2];           // (rz+8)*33
            zp[265] = acc[nf][3];
        }
        __syncthreads();

        // ---- reduce 4 kq partials + Xproj; gates; one cell per thread ----
        {
            float z[4];
            #pragma unroll
            for (int g = 0; g < 4; g++) {
                int e = gb * 33 + g * 8 + gj;
                z[g] = xs[gb * 32 + g * 8 + gj]
                     + zs[e] + zs[2112 + e] + zs[4224 + e] + zs[6336 + e];
            }
            float ig = sigm(z[0]);
            float fg = sigm(z[1]);
            float gg = tanha(z[2]);
            float og = sigm(z[3]);
            float cn = fg * creg + ig * gg;
            creg = cn;
            float h = og * tanha(cn);
            __nv_bfloat16 bh = __float2bfloat16(h);
            nhi[gb * H_ + u0 + gj] = bh;
            nlo[gb * H_ + u0 + gj] = __float2bfloat16(h - __bfloat162float(bh));
            if (s == T_ - 1) g_hfin[gb * H_ + u0 + gj] = h;
        }

        // ---- grid-wide barrier (release arrival, acquire spin) ----
        __threadfence();
        __syncthreads();
        if (tid == 0) {
            asm volatile("red.release.gpu.global.add.u32 [%0], 1;"
                         :: "l"(&g_bar[s]) : "memory");
            unsigned v;
            do {
                asm volatile("ld.acquire.gpu.global.u32 %0, [%1];"
                             : "=r"(v) : "l"(&g_bar[s]) : "memory");
            } while (v < NBLK_);
        }
        __syncthreads();
    }

    // ---- persist c state ----
    g_cst[gb * H_ + u0 + gj] = creg;
}

// ------------------------------- output -------------------------------------
__global__ void write_out(float* __restrict__ out) {
    int i = blockIdx.x * blockDim.x + threadIdx.x;
    if (i < B_ * H_) {
        out[i] = g_hfin[i];
        out[B_ * H_ + i] = g_cst[i];
    }
}

extern "C" void kernel_launch(void* const* d_in, const int* in_sizes, int n_in,
                              void* d_out, int out_size) {
    (void)in_sizes; (void)n_in; (void)out_size;
    const int*   src  = (const int*)d_in[0];
    const float* emb  = (const float*)d_in[1];
    const float* Wih  = (const float*)d_in[2];
    const float* Whh  = (const float*)d_in[3];
    const float* bias = (const float*)d_in[4];
    float* out = (float*)d_out;

    cudaFuncSetAttribute(lstm_chunk, cudaFuncAttributeMaxDynamicSharedMemorySize,
                         SMEM_BYTES_);

    // ONE init launch: with prep, this places lstm_chunk at launch #6 so
    // ncu's "-s 5 -c 1" captures it.
    init_state<<<(B_ * H_ + 255) / 256, 256>>>();
    prep_bf16<<<(V_ * E_ + 255) / 256, 256>>>(emb, Wih);
    for (int t0 = 0; t0 < T_; t0 += TCH_) {
        xproj_hmma<<<dim3(G4_ / 64, (TCH_ * B_) / 128), 256>>>(src, bias, t0);
        lstm_chunk<<<NBLK_, 512, SMEM_BYTES_>>>(Whh, t0);
    }
    write_out<<<(B_ * H_ + 255) / 256, 256>>>(out);
}